// round 13
// baseline (speedup 1.0000x reference)
#include <cuda_runtime.h>
#include <cuda_fp16.h>
#include <math.h>
#include <cstdint>

// ---------------------------------------------------------------------------
// Problem constants
// ---------------------------------------------------------------------------
#define BB 4
#define SS 2048
#define DD 1024
#define HH 16
#define DH 64
#define FF 4096
#define NN (BB * SS)
#define EPS 1e-6f
#define THRESH 0.15f
#define SCALE 0.125f
#define QSCALE 0.1803368801111f   // SCALE * log2(e); folded into Q at projection

// ---------------------------------------------------------------------------
// Scratch (half activations, half weights; fp32 residual path)
// ---------------------------------------------------------------------------
__device__ __half g_x2  [NN * DD];
__device__ __half g_q   [NN * DD];
__device__ __half g_k   [NN * DD];
__device__ __half g_v   [NN * DD];
__device__ float  g_attn[NN * DD];
__device__ float  g_xres[NN * DD];
__device__ __half g_x2b [NN * DD];
__device__ __half g_h   [NN * FF];
__device__ __half g_wqh [DD * DD];
__device__ __half g_wkh [DD * DD];
__device__ __half g_wvh [DD * DD];
__device__ __half g_w1h [FF * DD];
__device__ __half g_w2h [DD * FF];

// ---------------------------------------------------------------------------
// helpers
// ---------------------------------------------------------------------------
__device__ __forceinline__ uint32_t smem_u32(const void* p) {
    uint32_t a;
    asm("{ .reg .u64 t; cvta.to.shared.u64 t, %1; cvt.u32.u64 %0, t; }"
        : "=r"(a) : "l"(p));
    return a;
}

__device__ __forceinline__ void cp16(uint32_t dst, const void* src) {
    asm volatile("cp.async.cg.shared.global [%0], [%1], 16;" :: "r"(dst), "l"(src));
}
#define CP_COMMIT() asm volatile("cp.async.commit_group;" ::: "memory")
#define CP_WAIT1()  asm volatile("cp.async.wait_group 1;" ::: "memory")
#define CP_WAIT2()  asm volatile("cp.async.wait_group 2;" ::: "memory")
#define CP_WAIT3()  asm volatile("cp.async.wait_group 3;" ::: "memory")

__device__ __forceinline__ void mma_f16(float c[4], const uint32_t a[4],
                                        uint32_t b0, uint32_t b1) {
    asm volatile(
        "mma.sync.aligned.m16n8k16.row.col.f32.f16.f16.f32 "
        "{%0,%1,%2,%3}, {%4,%5,%6,%7}, {%8,%9}, {%0,%1,%2,%3};"
        : "+f"(c[0]), "+f"(c[1]), "+f"(c[2]), "+f"(c[3])
        : "r"(a[0]), "r"(a[1]), "r"(a[2]), "r"(a[3]), "r"(b0), "r"(b1));
}

#define LDMX4(r, addr)                                                        \
    asm volatile("ldmatrix.sync.aligned.m8n8.x4.shared.b16 {%0,%1,%2,%3}, [%4];" \
        : "=r"((r)[0]), "=r"((r)[1]), "=r"((r)[2]), "=r"((r)[3]) : "r"(addr))
#define LDMX4T(r, addr)                                                       \
    asm volatile("ldmatrix.sync.aligned.m8n8.x4.trans.shared.b16 {%0,%1,%2,%3}, [%4];" \
        : "=r"((r)[0]), "=r"((r)[1]), "=r"((r)[2]), "=r"((r)[3]) : "r"(addr))

// ---------------------------------------------------------------------------
// fused float -> half conversion for ALL weights in one launch
// ---------------------------------------------------------------------------
#define NQKV4 (DD * DD / 4)     // 262144
#define NFF4  (FF * DD / 4)     // 1048576
#define NCVT4 (3 * NQKV4 + 2 * NFF4)

__global__ __launch_bounds__(256) void cvt_all_kernel(
    const float* __restrict__ wq, const float* __restrict__ wk,
    const float* __restrict__ wv, const float* __restrict__ w1,
    const float* __restrict__ w2,
    __half* __restrict__ hq, __half* __restrict__ hk,
    __half* __restrict__ hv, __half* __restrict__ h1,
    __half* __restrict__ h2)
{
    int i = blockIdx.x * 256 + threadIdx.x;
    if (i >= NCVT4) return;
    const float* src;
    __half* dst;
    int off;
    if (i < 3 * NQKV4) {
        const int w = i / NQKV4;
        off = i - w * NQKV4;
        src = (w == 0) ? wq : (w == 1) ? wk : wv;
        dst = (w == 0) ? hq : (w == 1) ? hk : hv;
    } else {
        int j = i - 3 * NQKV4;
        if (j < NFF4) { src = w1; dst = h1; off = j; }
        else          { src = w2; dst = h2; off = j - NFF4; }
    }
    float4 v = ((const float4*)src)[off];
    __half2 h0 = __floats2half2_rn(v.x, v.y);
    __half2 h1v = __floats2half2_rn(v.z, v.w);
    uint2 pk;
    pk.x = *(uint32_t*)&h0;
    pk.y = *(uint32_t*)&h1v;
    ((uint2*)dst)[off] = pk;
}

// ---------------------------------------------------------------------------
// fp16 mma.sync GEMM — R8/R11 structure (unchanged).
// mode 0: half out scaled by oscale (Q folding). mode 1: relu half out.
// mode 2: float out + resid.
// ---------------------------------------------------------------------------
#define MBK  64
#define MBM  128
#define MBN  256
#define APADH 36
#define ASTG (MBM * APADH)
#define BSTG (MBN * APADH)
#define NSTAGE 3
#define GSMEM_BYTES ((ASTG + BSTG) * NSTAGE * 4)

__global__ __launch_bounds__(256, 1) void mma_gemm(
    const __half* __restrict__ A,
    const __half* __restrict__ W0, const __half* __restrict__ W1, const __half* __restrict__ W2,
    const float* __restrict__ bi0, const float* __restrict__ bi1, const float* __restrict__ bi2,
    const float* __restrict__ resid,
    __half* __restrict__ H0, __half* __restrict__ H1, __half* __restrict__ H2,
    float* __restrict__ Cf,
    int K, int ldc, int mode, float oscale0)
{
    extern __shared__ __align__(16) uint32_t smu[];
    const uint32_t sAb = smem_u32(smu);
    const uint32_t sBb = sAb + NSTAGE * ASTG * 4;

    const __half* W    = (blockIdx.z == 0) ? W0  : (blockIdx.z == 1) ? W1  : W2;
    const float*  bias = (blockIdx.z == 0) ? bi0 : (blockIdx.z == 1) ? bi1 : bi2;
    __half*       Ch   = (blockIdx.z == 0) ? H0  : (blockIdx.z == 1) ? H1  : H2;
    const float oscale = (blockIdx.z == 0) ? oscale0 : 1.0f;

    const int tid    = threadIdx.x;
    const int wid    = tid >> 5;
    const int lane   = tid & 31;
    const int warp_m = wid >> 2;
    const int warp_n = wid & 3;
    const int g      = lane >> 2;
    const int t4     = lane & 3;

    const int row0 = blockIdx.y * MBM;
    const int col0 = blockIdx.x * MBN;

    const __half* gA = A + (size_t)row0 * K;
    const __half* gW = W + (size_t)col0 * K;

    const int lrow = tid >> 3;
    const int lch  = tid & 7;

    const uint32_t a_lane = (uint32_t)((warp_m * 64 + (lane & 15)) * APADH + ((lane >> 4) << 2));
    const uint32_t b_lane = (uint32_t)((warp_n * 64 + (lane & 7) + ((lane >> 4) << 3)) * APADH
                                       + (((lane >> 3) & 1) << 2));

    float acc[4][8][4];
    #pragma unroll
    for (int mt = 0; mt < 4; mt++)
        #pragma unroll
        for (int nt = 0; nt < 8; nt++)
            #pragma unroll
            for (int j = 0; j < 4; j++) acc[mt][nt][j] = 0.0f;

    const int NT = K / MBK;

    auto load_stage = [&](int buf, int kt) {
        const size_t kof = (size_t)kt * MBK + lch * 8;
        const uint32_t da = sAb + (buf * ASTG) * 4;
        const uint32_t db = sBb + (buf * BSTG) * 4;
        #pragma unroll
        for (int i = 0; i < 4; i++) {
            const int r = lrow + 32 * i;
            cp16(da + (r * APADH + lch * 4) * 4, gA + (size_t)r * K + kof);
        }
        #pragma unroll
        for (int i = 0; i < 8; i++) {
            const int r = lrow + 32 * i;
            cp16(db + (r * APADH + lch * 4) * 4, gW + (size_t)r * K + kof);
        }
    };

    load_stage(0, 0);
    CP_COMMIT();
    load_stage(1, 1);
    CP_COMMIT();

    int buf = 0;
    for (int t = 0; t < NT; t++) {
        CP_WAIT1();
        __syncthreads();

        const uint32_t abase = sAb + (buf * ASTG + a_lane) * 4;
        const uint32_t bbase = sBb + (buf * BSTG + b_lane) * 4;

        #pragma unroll
        for (int ks = 0; ks < 4; ks++) {
            uint32_t a[4][4], bb[4][4];
            #pragma unroll
            for (int mt = 0; mt < 4; mt++)
                LDMX4(a[mt], abase + (mt * 16 * APADH + ks * 8) * 4);
            #pragma unroll
            for (int ntp = 0; ntp < 4; ntp++)
                LDMX4(bb[ntp], bbase + (ntp * 16 * APADH + ks * 8) * 4);
            #pragma unroll
            for (int mt = 0; mt < 4; mt++)
                #pragma unroll
                for (int ntp = 0; ntp < 4; ntp++) {
                    mma_f16(acc[mt][2 * ntp],     a[mt], bb[ntp][0], bb[ntp][1]);
                    mma_f16(acc[mt][2 * ntp + 1], a[mt], bb[ntp][2], bb[ntp][3]);
                }
        }

        if (t + 2 < NT) {
            load_stage((buf + 2 >= NSTAGE) ? buf + 2 - NSTAGE : buf + 2, t + 2);
        }
        CP_COMMIT();
        buf = (buf + 1 == NSTAGE) ? 0 : buf + 1;
    }

    const int rb = row0 + warp_m * 64 + g;
    const int cb = col0 + warp_n * 64 + t4 * 2;
    #pragma unroll
    for (int mt = 0; mt < 4; mt++) {
        const int r = rb + mt * 16;
        #pragma unroll
        for (int nt = 0; nt < 8; nt++) {
            const int c = cb + nt * 8;
            const float2 bv = *(const float2*)(bias + c);
            float2 v0, v1;
            v0.x = acc[mt][nt][0] + bv.x;
            v0.y = acc[mt][nt][1] + bv.y;
            v1.x = acc[mt][nt][2] + bv.x;
            v1.y = acc[mt][nt][3] + bv.y;
            if (mode == 2) {
                const float2 r0 = *(const float2*)(resid + (size_t)r * ldc + c);
                const float2 r1 = *(const float2*)(resid + (size_t)(r + 8) * ldc + c);
                v0.x += r0.x; v0.y += r0.y;
                v1.x += r1.x; v1.y += r1.y;
                *(float2*)(Cf + (size_t)r * ldc + c)       = v0;
                *(float2*)(Cf + (size_t)(r + 8) * ldc + c) = v1;
            } else {
                if (mode == 1) {
                    v0.x = fmaxf(v0.x, 0.0f); v0.y = fmaxf(v0.y, 0.0f);
                    v1.x = fmaxf(v1.x, 0.0f); v1.y = fmaxf(v1.y, 0.0f);
                } else {
                    v0.x *= oscale; v0.y *= oscale;
                    v1.x *= oscale; v1.y *= oscale;
                }
                __half2 h0 = __floats2half2_rn(v0.x, v0.y);
                __half2 h1 = __floats2half2_rn(v1.x, v1.y);
                *(uint32_t*)(Ch + (size_t)r * ldc + c)       = *(uint32_t*)&h0;
                *(uint32_t*)(Ch + (size_t)(r + 8) * ldc + c) = *(uint32_t*)&h1;
            }
        }
    }
}

// ---------------------------------------------------------------------------
// LayerNorm — half output; fp32 residual in/out; shfl-based reduction (R11)
// ---------------------------------------------------------------------------
__global__ __launch_bounds__(256) void ln_kernel(
    const float* __restrict__ x,
    const float* __restrict__ resid,
    float*       __restrict__ out_res,
    __half*      __restrict__ out_norm,
    const float* __restrict__ alpha,
    const float* __restrict__ beta,
    int apply_mask)
{
    __shared__ float red[18];
    const int n    = blockIdx.x;
    const int tid  = threadIdx.x;
    const int lane = tid & 31;
    const int wrp  = tid >> 5;
    const size_t off = (size_t)n * DD;
    const int d4 = tid * 4;

    float4 xv = *(const float4*)(x + off + d4);
    if (resid) {
        float4 rv = *(const float4*)(resid + off + d4);
        xv.x += rv.x; xv.y += rv.y; xv.z += rv.z; xv.w += rv.w;
    }
    if (out_res) *(float4*)(out_res + off + d4) = xv;

    float s = xv.x + xv.y + xv.z + xv.w;
    #pragma unroll
    for (int o = 16; o > 0; o >>= 1) s += __shfl_xor_sync(0xffffffff, s, o);
    if (lane == 0) red[wrp] = s;
    __syncthreads();
    if (tid < 8) {
        float v = red[tid];
        #pragma unroll
        for (int o = 4; o > 0; o >>= 1) v += __shfl_xor_sync(0x000000ff, v, o);
        if (tid == 0) red[16] = v;
    }
    __syncthreads();
    const float mu = red[16] * (1.0f / DD);

    float dx0 = xv.x - mu, dx1 = xv.y - mu, dx2 = xv.z - mu, dx3 = xv.w - mu;
    float q = dx0*dx0 + dx1*dx1 + dx2*dx2 + dx3*dx3;
    #pragma unroll
    for (int o = 16; o > 0; o >>= 1) q += __shfl_xor_sync(0xffffffff, q, o);
    if (lane == 0) red[8 + wrp] = q;
    __syncthreads();
    if (tid < 8) {
        float v = red[8 + tid];
        #pragma unroll
        for (int o = 4; o > 0; o >>= 1) v += __shfl_xor_sync(0x000000ff, v, o);
        if (tid == 0) red[17] = v;
    }
    __syncthreads();
    const float var = red[17] * (1.0f / (DD - 1));
    const float inv = 1.0f / (sqrtf(var) + EPS);

    float4 av = *(const float4*)(alpha + d4);
    float4 bv = *(const float4*)(beta  + d4);
    float4 y;
    y.x = av.x * dx0 * inv + bv.x;
    y.y = av.y * dx1 * inv + bv.y;
    y.z = av.z * dx2 * inv + bv.z;
    y.w = av.w * dx3 * inv + bv.w;
    if (apply_mask) {
        if (y.x < THRESH) y.x = 0.0f;
        if (y.y < THRESH) y.y = 0.0f;
        if (y.z < THRESH) y.z = 0.0f;
        if (y.w < THRESH) y.w = 0.0f;
    }
    __half2 h0 = __floats2half2_rn(y.x, y.y);
    __half2 h1 = __floats2half2_rn(y.z, y.w);
    uint2 pk;
    pk.x = *(uint32_t*)&h0;
    pk.y = *(uint32_t*)&h1;
    *(uint2*)(out_norm + off + d4) = pk;
}

// ---------------------------------------------------------------------------
// FlashAttention-2 fp16 attention — base-2 softmax (scale folded into Q),
// 4-slot KV ring with prefetch-3 -> ONE __syncthreads per tile,
// running global pointers for cp.async.
// ---------------------------------------------------------------------------
#define FHPAD 36
#define FQ_U32  (128 * FHPAD)                 // 4608
#define FKV_U32 (64 * FHPAD)                  // 2304
#define SM_Q  0
#define SM_K0 (FQ_U32)                        // 4 K slots
#define SM_V0 (FQ_U32 + 4 * FKV_U32)          // 4 V slots
#define FATTN_BYTES ((FQ_U32 + 8 * FKV_U32) * 4)   // 92160 B

__global__ __launch_bounds__(256, 2) void attn_mma(
    const __half* __restrict__ Q,
    const __half* __restrict__ Km,
    const __half* __restrict__ Vm,
    float*        __restrict__ O)
{
    extern __shared__ __align__(16) uint32_t smu[];
    const uint32_t sb = smem_u32(smu);

    const int qb  = blockIdx.x;
    const int bh  = blockIdx.y;
    const int b   = bh >> 4;
    const int h   = bh & 15;
    const int tid = threadIdx.x;
    const int lane = tid & 31;
    const int wid  = tid >> 5;
    const int g    = lane >> 2;
    const int t4   = lane & 3;

    const size_t base = (size_t)b * SS * DD + (size_t)h * DH;
    const int q0 = qb * 128;

    const uint32_t qa_lane = (uint32_t)((wid * 16 + (lane & 15)) * FHPAD + ((lane >> 4) << 2));
    const uint32_t kb_lane = (uint32_t)(((lane & 7) + ((lane >> 4) << 3)) * FHPAD
                                        + (((lane >> 3) & 1) << 2));
    const uint32_t vb_lane = (uint32_t)(((lane & 7) + (((lane >> 3) & 1) << 3)) * FHPAD
                                        + ((lane >> 4) << 2));

    // Q load (group 0)
    #pragma unroll
    for (int i = 0; i < 4; i++) {
        const int t = tid + 256 * i;
        const int r = t >> 3, c = t & 7;
        cp16(sb + (SM_Q + r * FHPAD + c * 4) * 4,
             Q + base + (size_t)(q0 + r) * DD + c * 8);
    }
    CP_COMMIT();

    // KV running pointers: thread covers rows r0 and r0+32, col chunk cc
    const int r0 = tid >> 3;
    const int cc = tid & 7;
    const __half* kg = Km + base + (size_t)r0 * DD + cc * 8;
    const __half* vg = Vm + base + (size_t)r0 * DD + cc * 8;
    const size_t rstep = (size_t)32 * DD;     // second row of this thread
    const size_t tstep = (size_t)64 * DD;     // advance one 64-key tile
    const uint32_t so0 = (uint32_t)((r0 * FHPAD + cc * 4) * 4);
    const uint32_t so1 = (uint32_t)(((r0 + 32) * FHPAD + cc * 4) * 4);

    auto load_kv = [&](int s) {
        const uint32_t kd = sb + (SM_K0 + s * FKV_U32) * 4;
        const uint32_t vd = sb + (SM_V0 + s * FKV_U32) * 4;
        cp16(kd + so0, kg);
        cp16(kd + so1, kg + rstep);
        cp16(vd + so0, vg);
        cp16(vd + so1, vg + rstep);
        kg += tstep;
        vg += tstep;
    };

    load_kv(0); CP_COMMIT();
    load_kv(1); CP_COMMIT();
    load_kv(2); CP_COMMIT();

    // wait for Q only (3 KV groups may remain outstanding)
    CP_WAIT3();
    __syncthreads();
    uint32_t qf[4][4];
    #pragma unroll
    for (int ks = 0; ks < 4; ks++)
        LDMX4(qf[ks], sb + (SM_Q + qa_lane + ks * 8) * 4);

    float m0 = -1e30f, m1 = -1e30f, l0 = 0.0f, l1 = 0.0f;
    float acc_o[8][4];
    #pragma unroll
    for (int nt = 0; nt < 8; nt++)
        #pragma unroll
        for (int j = 0; j < 4; j++) acc_o[nt][j] = 0.0f;

    for (int kt = 0; kt < SS / 64; kt++) {
        CP_WAIT2();          // kv(kt) complete
        __syncthreads();     // all warps' kv(kt) copies visible; all in iter kt
        const int s = kt & 3;

        // prefetch kv(kt+3) into slot (kt+3)&3 — untouched by iters kt..kt+2
        if (kt + 3 < SS / 64) load_kv((kt + 3) & 3);
        CP_COMMIT();

        // --- S (log2 units; Q pre-scaled) ---
        float accs[8][4];
        #pragma unroll
        for (int nt = 0; nt < 8; nt++)
            #pragma unroll
            for (int j = 0; j < 4; j++) accs[nt][j] = 0.0f;

        const uint32_t kbase = sb + (SM_K0 + s * FKV_U32 + kb_lane) * 4;
        #pragma unroll
        for (int ks = 0; ks < 4; ks++) {
            #pragma unroll
            for (int nt16 = 0; nt16 < 4; nt16++) {
                uint32_t bb[4];
                LDMX4(bb, kbase + (nt16 * 16 * FHPAD + ks * 8) * 4);
                mma_f16(accs[2 * nt16],     qf[ks], bb[0], bb[1]);
                mma_f16(accs[2 * nt16 + 1], qf[ks], bb[2], bb[3]);
            }
        }

        // --- warp-local online softmax (base 2) ---
        float nm0 = -1e30f, nm1 = -1e30f;
        #pragma unroll
        for (int nt = 0; nt < 8; nt++) {
            nm0 = fmaxf(nm0, fmaxf(accs[nt][0], accs[nt][1]));
            nm1 = fmaxf(nm1, fmaxf(accs[nt][2], accs[nt][3]));
        }
        nm0 = fmaxf(nm0, __shfl_xor_sync(0xffffffff, nm0, 1));
        nm0 = fmaxf(nm0, __shfl_xor_sync(0xffffffff, nm0, 2));
        nm1 = fmaxf(nm1, __shfl_xor_sync(0xffffffff, nm1, 1));
        nm1 = fmaxf(nm1, __shfl_xor_sync(0xffffffff, nm1, 2));
        nm0 = fmaxf(m0, nm0);
        nm1 = fmaxf(m1, nm1);
        const float corr0 = exp2f(m0 - nm0);
        const float corr1 = exp2f(m1 - nm1);
        m0 = nm0; m1 = nm1;

        float s0 = 0.0f, s1 = 0.0f;
        uint32_t ph[8][2];
        #pragma unroll
        for (int nt = 0; nt < 8; nt++) {
            const float e0 = exp2f(accs[nt][0] - m0);
            const float e1 = exp2f(accs[nt][1] - m0);
            const float e2 = exp2f(accs[nt][2] - m1);
            const float e3 = exp2f(accs[nt][3] - m1);
            s0 += e0 + e1; s1 += e2 + e3;
            __half2 h01 = __floats2half2_rn(e0, e1);
            __half2 h23 = __floats2half2_rn(e2, e3);
            ph[nt][0] = *(uint32_t*)&h01;
            ph[nt][1] = *(uint32_t*)&h23;
        }
        s0 += __shfl_xor_sync(0xffffffff, s0, 1);
        s0 += __shfl_xor_sync(0xffffffff, s0, 2);
        s1 += __shfl_xor_sync(0xffffffff, s1, 1);
        s1 += __shfl_xor_sync(0xffffffff, s1, 2);
        l0 = l0 * corr0 + s0;
        l1 = l1 * corr1 + s1;

        #pragma unroll
        for (int nt = 0; nt < 8; nt++) {
            acc_o[nt][0] *= corr0; acc_o[nt][1] *= corr0;
            acc_o[nt][2] *= corr1; acc_o[nt][3] *= corr1;
        }

        // --- acc_o += P V ---
        const uint32_t vbase = sb + (SM_V0 + s * FKV_U32 + vb_lane) * 4;
        #pragma unroll
        for (int ks = 0; ks < 4; ks++) {
            const uint32_t a[4] = { ph[2 * ks][0], ph[2 * ks][1],
                                    ph[2 * ks + 1][0], ph[2 * ks + 1][1] };
            #pragma unroll
            for (int d16 = 0; d16 < 4; d16++) {
                uint32_t bb[4];
                LDMX4T(bb, vbase + (ks * 16 * FHPAD + d16 * 8) * 4);
                mma_f16(acc_o[2 * d16],     a, bb[0], bb[1]);
                mma_f16(acc_o[2 * d16 + 1], a, bb[2], bb[3]);
            }
        }
        // no trailing sync: 4-slot ring guarantees no read/write overlap
    }

    // epilogue: divide by l, store fp32
    const float li0 = 1.0f / l0;
    const float li1 = 1.0f / l1;
    const int rr = q0 + wid * 16 + g;
    const size_t ro0 = base + (size_t)rr * DD;
    const size_t ro1 = base + (size_t)(rr + 8) * DD;
    #pragma unroll
    for (int nt = 0; nt < 8; nt++) {
        const int c = nt * 8 + 2 * t4;
        float2 lo, hi;
        lo.x = acc_o[nt][0] * li0; lo.y = acc_o[nt][1] * li0;
        hi.x = acc_o[nt][2] * li1; hi.y = acc_o[nt][3] * li1;
        *(float2*)(O + ro0 + c) = lo;
        *(float2*)(O + ro1 + c) = hi;
    }
}

// ---------------------------------------------------------------------------
// launch (sequential, default stream)
// ---------------------------------------------------------------------------
extern "C" void kernel_launch(void* const* d_in, const int* in_sizes, int n_in,
                              void* d_out, int out_size)
{
    const float* x      = (const float*)d_in[0];
    const float* alpha1 = (const float*)d_in[1];
    const float* bias1  = (const float*)d_in[2];
    const float* alpha2 = (const float*)d_in[3];
    const float* bias2  = (const float*)d_in[4];
    const float* wq     = (const float*)d_in[5];
    const float* bq     = (const float*)d_in[6];
    const float* wk     = (const float*)d_in[7];
    const float* bk     = (const float*)d_in[8];
    const float* wv     = (const float*)d_in[9];
    const float* bv     = (const float*)d_in[10];
    const float* w1     = (const float*)d_in[11];
    const float* b1     = (const float*)d_in[12];
    const float* w2     = (const float*)d_in[13];
    const float* b2     = (const float*)d_in[14];
    float* out = (float*)d_out;

    __half *p_x2, *p_q, *p_k, *p_v, *p_x2b, *p_h;
    __half *p_wqh, *p_wkh, *p_wvh, *p_w1h, *p_w2h;
    float *p_attn, *p_xres;
    cudaGetSymbolAddress((void**)&p_x2,   g_x2);
    cudaGetSymbolAddress((void**)&p_q,    g_q);
    cudaGetSymbolAddress((void**)&p_k,    g_k);
    cudaGetSymbolAddress((void**)&p_v,    g_v);
    cudaGetSymbolAddress((void**)&p_attn, g_attn);
    cudaGetSymbolAddress((void**)&p_xres, g_xres);
    cudaGetSymbolAddress((void**)&p_x2b,  g_x2b);
    cudaGetSymbolAddress((void**)&p_h,    g_h);
    cudaGetSymbolAddress((void**)&p_wqh,  g_wqh);
    cudaGetSymbolAddress((void**)&p_wkh,  g_wkh);
    cudaGetSymbolAddress((void**)&p_wvh,  g_wvh);
    cudaGetSymbolAddress((void**)&p_w1h,  g_w1h);
    cudaGetSymbolAddress((void**)&p_w2h,  g_w2h);

    cudaFuncSetAttribute(attn_mma,
                         cudaFuncAttributeMaxDynamicSharedMemorySize, FATTN_BYTES);
    cudaFuncSetAttribute(mma_gemm,
                         cudaFuncAttributeMaxDynamicSharedMemorySize, GSMEM_BYTES);

    // 0) convert all weights to half (single fused launch)
    cvt_all_kernel<<<(NCVT4 + 255) / 256, 256>>>(
        wq, wk, wv, w1, w2, p_wqh, p_wkh, p_wvh, p_w1h, p_w2h);

    // 1) norm1 (half out)
    ln_kernel<<<NN, 256>>>(x, nullptr, nullptr, p_x2, alpha1, bias1, 0);

    // 2) fused q,k,v projections; Q output pre-scaled by SCALE*log2(e)
    mma_gemm<<<dim3(DD / MBN, NN / MBM, 3), 256, GSMEM_BYTES>>>(
        p_x2, p_wqh, p_wkh, p_wvh, bq, bk, bv, nullptr,
        p_q, p_k, p_v, nullptr, DD, DD, 0, QSCALE);

    // 3) attention (fp32 out)
    attn_mma<<<dim3(SS / 128, BB * HH), 256, FATTN_BYTES>>>(p_q, p_k, p_v, p_attn);

    // 4) residual + norm2 + mask
    ln_kernel<<<NN, 256>>>(x, p_attn, p_xres, p_x2b, alpha2, bias2, 1);

    // 5) ffn1 + relu (half out)
    mma_gemm<<<dim3(FF / MBN, NN / MBM, 1), 256, GSMEM_BYTES>>>(
        p_x2b, p_w1h, p_w1h, p_w1h, b1, b1, b1, nullptr,
        p_h, p_h, p_h, nullptr, DD, FF, 1, 1.0f);

    // 6) ffn2 + bias + residual -> out (fp32)
    mma_gemm<<<dim3(DD / MBN, NN / MBM, 1), 256, GSMEM_BYTES>>>(
        p_h, p_w2h, p_w2h, p_w2h, b2, b2, b2, p_xres,
        nullptr, nullptr, nullptr, out, FF, DD, 2, 1.0f);
}

// round 14
// speedup vs baseline: 1.0072x; 1.0072x over previous
#include <cuda_runtime.h>
#include <cuda_fp16.h>
#include <math.h>
#include <cstdint>

// ---------------------------------------------------------------------------
// Problem constants
// ---------------------------------------------------------------------------
#define BB 4
#define SS 2048
#define DD 1024
#define HH 16
#define DH 64
#define FF 4096
#define NN (BB * SS)
#define EPS 1e-6f
#define THRESH 0.15f
#define SCALE 0.125f
#define QSCALE 0.1803368801111f   // SCALE * log2(e); folded into Q at projection
#define ONES_H2 0x3C003C00u       // half2(1.0, 1.0)

// ---------------------------------------------------------------------------
// Scratch (half activations, half weights; fp32 residual path)
// ---------------------------------------------------------------------------
__device__ __half g_x2  [NN * DD];
__device__ __half g_q   [NN * DD];
__device__ __half g_k   [NN * DD];
__device__ __half g_v   [NN * DD];
__device__ float  g_attn[NN * DD];
__device__ float  g_xres[NN * DD];
__device__ __half g_x2b [NN * DD];
__device__ __half g_h   [NN * FF];
__device__ __half g_wqh [DD * DD];
__device__ __half g_wkh [DD * DD];
__device__ __half g_wvh [DD * DD];
__device__ __half g_w1h [FF * DD];
__device__ __half g_w2h [DD * FF];

// ---------------------------------------------------------------------------
// helpers
// ---------------------------------------------------------------------------
__device__ __forceinline__ uint32_t smem_u32(const void* p) {
    uint32_t a;
    asm("{ .reg .u64 t; cvta.to.shared.u64 t, %1; cvt.u32.u64 %0, t; }"
        : "=r"(a) : "l"(p));
    return a;
}

__device__ __forceinline__ void cp16(uint32_t dst, const void* src) {
    asm volatile("cp.async.cg.shared.global [%0], [%1], 16;" :: "r"(dst), "l"(src));
}
#define CP_COMMIT() asm volatile("cp.async.commit_group;" ::: "memory")
#define CP_WAIT1()  asm volatile("cp.async.wait_group 1;" ::: "memory")
#define CP_WAIT2()  asm volatile("cp.async.wait_group 2;" ::: "memory")

__device__ __forceinline__ void mma_f16(float c[4], const uint32_t a[4],
                                        uint32_t b0, uint32_t b1) {
    asm volatile(
        "mma.sync.aligned.m16n8k16.row.col.f32.f16.f16.f32 "
        "{%0,%1,%2,%3}, {%4,%5,%6,%7}, {%8,%9}, {%0,%1,%2,%3};"
        : "+f"(c[0]), "+f"(c[1]), "+f"(c[2]), "+f"(c[3])
        : "r"(a[0]), "r"(a[1]), "r"(a[2]), "r"(a[3]), "r"(b0), "r"(b1));
}

#define LDMX4(r, addr)                                                        \
    asm volatile("ldmatrix.sync.aligned.m8n8.x4.shared.b16 {%0,%1,%2,%3}, [%4];" \
        : "=r"((r)[0]), "=r"((r)[1]), "=r"((r)[2]), "=r"((r)[3]) : "r"(addr))
#define LDMX4T(r, addr)                                                       \
    asm volatile("ldmatrix.sync.aligned.m8n8.x4.trans.shared.b16 {%0,%1,%2,%3}, [%4];" \
        : "=r"((r)[0]), "=r"((r)[1]), "=r"((r)[2]), "=r"((r)[3]) : "r"(addr))

#define EX2_F16X2(d, a) \
    asm("ex2.approx.f16x2 %0, %1;" : "=r"(d) : "r"(a))

// ---------------------------------------------------------------------------
// fused float -> half conversion for ALL weights in one launch
// ---------------------------------------------------------------------------
#define NQKV4 (DD * DD / 4)     // 262144
#define NFF4  (FF * DD / 4)     // 1048576
#define NCVT4 (3 * NQKV4 + 2 * NFF4)

__global__ __launch_bounds__(256) void cvt_all_kernel(
    const float* __restrict__ wq, const float* __restrict__ wk,
    const float* __restrict__ wv, const float* __restrict__ w1,
    const float* __restrict__ w2,
    __half* __restrict__ hq, __half* __restrict__ hk,
    __half* __restrict__ hv, __half* __restrict__ h1,
    __half* __restrict__ h2)
{
    int i = blockIdx.x * 256 + threadIdx.x;
    if (i >= NCVT4) return;
    const float* src;
    __half* dst;
    int off;
    if (i < 3 * NQKV4) {
        const int w = i / NQKV4;
        off = i - w * NQKV4;
        src = (w == 0) ? wq : (w == 1) ? wk : wv;
        dst = (w == 0) ? hq : (w == 1) ? hk : hv;
    } else {
        int j = i - 3 * NQKV4;
        if (j < NFF4) { src = w1; dst = h1; off = j; }
        else          { src = w2; dst = h2; off = j - NFF4; }
    }
    float4 v = ((const float4*)src)[off];
    __half2 h0 = __floats2half2_rn(v.x, v.y);
    __half2 h1v = __floats2half2_rn(v.z, v.w);
    uint2 pk;
    pk.x = *(uint32_t*)&h0;
    pk.y = *(uint32_t*)&h1v;
    ((uint2*)dst)[off] = pk;
}

// ---------------------------------------------------------------------------
// fp16 mma.sync GEMM — R8/R12 structure (unchanged).
// mode 0: half out scaled by oscale (Q folding). mode 1: relu half out.
// mode 2: float out + resid.
// ---------------------------------------------------------------------------
#define MBK  64
#define MBM  128
#define MBN  256
#define APADH 36
#define ASTG (MBM * APADH)
#define BSTG (MBN * APADH)
#define NSTAGE 3
#define GSMEM_BYTES ((ASTG + BSTG) * NSTAGE * 4)

__global__ __launch_bounds__(256, 1) void mma_gemm(
    const __half* __restrict__ A,
    const __half* __restrict__ W0, const __half* __restrict__ W1, const __half* __restrict__ W2,
    const float* __restrict__ bi0, const float* __restrict__ bi1, const float* __restrict__ bi2,
    const float* __restrict__ resid,
    __half* __restrict__ H0, __half* __restrict__ H1, __half* __restrict__ H2,
    float* __restrict__ Cf,
    int K, int ldc, int mode, float oscale0)
{
    extern __shared__ __align__(16) uint32_t smu[];
    const uint32_t sAb = smem_u32(smu);
    const uint32_t sBb = sAb + NSTAGE * ASTG * 4;

    const __half* W    = (blockIdx.z == 0) ? W0  : (blockIdx.z == 1) ? W1  : W2;
    const float*  bias = (blockIdx.z == 0) ? bi0 : (blockIdx.z == 1) ? bi1 : bi2;
    __half*       Ch   = (blockIdx.z == 0) ? H0  : (blockIdx.z == 1) ? H1  : H2;
    const float oscale = (blockIdx.z == 0) ? oscale0 : 1.0f;

    const int tid    = threadIdx.x;
    const int wid    = tid >> 5;
    const int lane   = tid & 31;
    const int warp_m = wid >> 2;
    const int warp_n = wid & 3;
    const int g      = lane >> 2;
    const int t4     = lane & 3;

    const int row0 = blockIdx.y * MBM;
    const int col0 = blockIdx.x * MBN;

    const __half* gA = A + (size_t)row0 * K;
    const __half* gW = W + (size_t)col0 * K;

    const int lrow = tid >> 3;
    const int lch  = tid & 7;

    const uint32_t a_lane = (uint32_t)((warp_m * 64 + (lane & 15)) * APADH + ((lane >> 4) << 2));
    const uint32_t b_lane = (uint32_t)((warp_n * 64 + (lane & 7) + ((lane >> 4) << 3)) * APADH
                                       + (((lane >> 3) & 1) << 2));

    float acc[4][8][4];
    #pragma unroll
    for (int mt = 0; mt < 4; mt++)
        #pragma unroll
        for (int nt = 0; nt < 8; nt++)
            #pragma unroll
            for (int j = 0; j < 4; j++) acc[mt][nt][j] = 0.0f;

    const int NT = K / MBK;

    auto load_stage = [&](int buf, int kt) {
        const size_t kof = (size_t)kt * MBK + lch * 8;
        const uint32_t da = sAb + (buf * ASTG) * 4;
        const uint32_t db = sBb + (buf * BSTG) * 4;
        #pragma unroll
        for (int i = 0; i < 4; i++) {
            const int r = lrow + 32 * i;
            cp16(da + (r * APADH + lch * 4) * 4, gA + (size_t)r * K + kof);
        }
        #pragma unroll
        for (int i = 0; i < 8; i++) {
            const int r = lrow + 32 * i;
            cp16(db + (r * APADH + lch * 4) * 4, gW + (size_t)r * K + kof);
        }
    };

    load_stage(0, 0);
    CP_COMMIT();
    load_stage(1, 1);
    CP_COMMIT();

    int buf = 0;
    for (int t = 0; t < NT; t++) {
        CP_WAIT1();
        __syncthreads();

        const uint32_t abase = sAb + (buf * ASTG + a_lane) * 4;
        const uint32_t bbase = sBb + (buf * BSTG + b_lane) * 4;

        #pragma unroll
        for (int ks = 0; ks < 4; ks++) {
            uint32_t a[4][4], bb[4][4];
            #pragma unroll
            for (int mt = 0; mt < 4; mt++)
                LDMX4(a[mt], abase + (mt * 16 * APADH + ks * 8) * 4);
            #pragma unroll
            for (int ntp = 0; ntp < 4; ntp++)
                LDMX4(bb[ntp], bbase + (ntp * 16 * APADH + ks * 8) * 4);
            #pragma unroll
            for (int mt = 0; mt < 4; mt++)
                #pragma unroll
                for (int ntp = 0; ntp < 4; ntp++) {
                    mma_f16(acc[mt][2 * ntp],     a[mt], bb[ntp][0], bb[ntp][1]);
                    mma_f16(acc[mt][2 * ntp + 1], a[mt], bb[ntp][2], bb[ntp][3]);
                }
        }

        if (t + 2 < NT) {
            load_stage((buf + 2 >= NSTAGE) ? buf + 2 - NSTAGE : buf + 2, t + 2);
        }
        CP_COMMIT();
        buf = (buf + 1 == NSTAGE) ? 0 : buf + 1;
    }

    const int rb = row0 + warp_m * 64 + g;
    const int cb = col0 + warp_n * 64 + t4 * 2;
    #pragma unroll
    for (int mt = 0; mt < 4; mt++) {
        const int r = rb + mt * 16;
        #pragma unroll
        for (int nt = 0; nt < 8; nt++) {
            const int c = cb + nt * 8;
            const float2 bv = *(const float2*)(bias + c);
            float2 v0, v1;
            v0.x = acc[mt][nt][0] + bv.x;
            v0.y = acc[mt][nt][1] + bv.y;
            v1.x = acc[mt][nt][2] + bv.x;
            v1.y = acc[mt][nt][3] + bv.y;
            if (mode == 2) {
                const float2 r0 = *(const float2*)(resid + (size_t)r * ldc + c);
                const float2 r1 = *(const float2*)(resid + (size_t)(r + 8) * ldc + c);
                v0.x += r0.x; v0.y += r0.y;
                v1.x += r1.x; v1.y += r1.y;
                *(float2*)(Cf + (size_t)r * ldc + c)       = v0;
                *(float2*)(Cf + (size_t)(r + 8) * ldc + c) = v1;
            } else {
                if (mode == 1) {
                    v0.x = fmaxf(v0.x, 0.0f); v0.y = fmaxf(v0.y, 0.0f);
                    v1.x = fmaxf(v1.x, 0.0f); v1.y = fmaxf(v1.y, 0.0f);
                } else {
                    v0.x *= oscale; v0.y *= oscale;
                    v1.x *= oscale; v1.y *= oscale;
                }
                __half2 h0 = __floats2half2_rn(v0.x, v0.y);
                __half2 h1 = __floats2half2_rn(v1.x, v1.y);
                *(uint32_t*)(Ch + (size_t)r * ldc + c)       = *(uint32_t*)&h0;
                *(uint32_t*)(Ch + (size_t)(r + 8) * ldc + c) = *(uint32_t*)&h1;
            }
        }
    }
}

// ---------------------------------------------------------------------------
// LayerNorm — half output; fp32 residual in/out; shfl-based reduction (R11)
// ---------------------------------------------------------------------------
__global__ __launch_bounds__(256) void ln_kernel(
    const float* __restrict__ x,
    const float* __restrict__ resid,
    float*       __restrict__ out_res,
    __half*      __restrict__ out_norm,
    const float* __restrict__ alpha,
    const float* __restrict__ beta,
    int apply_mask)
{
    __shared__ float red[18];
    const int n    = blockIdx.x;
    const int tid  = threadIdx.x;
    const int lane = tid & 31;
    const int wrp  = tid >> 5;
    const size_t off = (size_t)n * DD;
    const int d4 = tid * 4;

    float4 xv = *(const float4*)(x + off + d4);
    if (resid) {
        float4 rv = *(const float4*)(resid + off + d4);
        xv.x += rv.x; xv.y += rv.y; xv.z += rv.z; xv.w += rv.w;
    }
    if (out_res) *(float4*)(out_res + off + d4) = xv;

    float s = xv.x + xv.y + xv.z + xv.w;
    #pragma unroll
    for (int o = 16; o > 0; o >>= 1) s += __shfl_xor_sync(0xffffffff, s, o);
    if (lane == 0) red[wrp] = s;
    __syncthreads();
    if (tid < 8) {
        float v = red[tid];
        #pragma unroll
        for (int o = 4; o > 0; o >>= 1) v += __shfl_xor_sync(0x000000ff, v, o);
        if (tid == 0) red[16] = v;
    }
    __syncthreads();
    const float mu = red[16] * (1.0f / DD);

    float dx0 = xv.x - mu, dx1 = xv.y - mu, dx2 = xv.z - mu, dx3 = xv.w - mu;
    float q = dx0*dx0 + dx1*dx1 + dx2*dx2 + dx3*dx3;
    #pragma unroll
    for (int o = 16; o > 0; o >>= 1) q += __shfl_xor_sync(0xffffffff, q, o);
    if (lane == 0) red[8 + wrp] = q;
    __syncthreads();
    if (tid < 8) {
        float v = red[8 + tid];
        #pragma unroll
        for (int o = 4; o > 0; o >>= 1) v += __shfl_xor_sync(0x000000ff, v, o);
        if (tid == 0) red[17] = v;
    }
    __syncthreads();
    const float var = red[17] * (1.0f / (DD - 1));
    const float inv = 1.0f / (sqrtf(var) + EPS);

    float4 av = *(const float4*)(alpha + d4);
    float4 bv = *(const float4*)(beta  + d4);
    float4 y;
    y.x = av.x * dx0 * inv + bv.x;
    y.y = av.y * dx1 * inv + bv.y;
    y.z = av.z * dx2 * inv + bv.z;
    y.w = av.w * dx3 * inv + bv.w;
    if (apply_mask) {
        if (y.x < THRESH) y.x = 0.0f;
        if (y.y < THRESH) y.y = 0.0f;
        if (y.z < THRESH) y.z = 0.0f;
        if (y.w < THRESH) y.w = 0.0f;
    }
    __half2 h0 = __floats2half2_rn(y.x, y.y);
    __half2 h1 = __floats2half2_rn(y.z, y.w);
    uint2 pk;
    pk.x = *(uint32_t*)&h0;
    pk.y = *(uint32_t*)&h1;
    *(uint2*)(out_norm + off + d4) = pk;
}

// ---------------------------------------------------------------------------
// FlashAttention-2 fp16 attention — R12 pipeline (2-slot, 2 barriers),
// base-2 softmax with ex2.approx.f16x2 and l computed via ones-column mma.
// ---------------------------------------------------------------------------
#define FHPAD 36
#define FQ_U32  (128 * FHPAD)
#define FKV_U32 (64 * FHPAD)
#define SM_Q  0
#define SM_K0 (FQ_U32)
#define SM_V0 (FQ_U32 + 2 * FKV_U32)
#define FATTN_BYTES ((FQ_U32 + 4 * FKV_U32) * 4)

__global__ __launch_bounds__(256, 2) void attn_mma(
    const __half* __restrict__ Q,
    const __half* __restrict__ Km,
    const __half* __restrict__ Vm,
    float*        __restrict__ O)
{
    extern __shared__ __align__(16) uint32_t smu[];
    const uint32_t sb = smem_u32(smu);

    const int qb  = blockIdx.x;
    const int bh  = blockIdx.y;
    const int b   = bh >> 4;
    const int h   = bh & 15;
    const int tid = threadIdx.x;
    const int lane = tid & 31;
    const int wid  = tid >> 5;
    const int g    = lane >> 2;
    const int t4   = lane & 3;

    const size_t base = (size_t)b * SS * DD + (size_t)h * DH;
    const int q0 = qb * 128;

    const uint32_t qa_lane = (uint32_t)((wid * 16 + (lane & 15)) * FHPAD + ((lane >> 4) << 2));
    const uint32_t kb_lane = (uint32_t)(((lane & 7) + ((lane >> 4) << 3)) * FHPAD
                                        + (((lane >> 3) & 1) << 2));
    const uint32_t vb_lane = (uint32_t)(((lane & 7) + (((lane >> 3) & 1) << 3)) * FHPAD
                                        + ((lane >> 4) << 2));

    #pragma unroll
    for (int i = 0; i < 4; i++) {
        const int t = tid + 256 * i;
        const int r = t >> 3, c = t & 7;
        cp16(sb + (SM_Q + r * FHPAD + c * 4) * 4,
             Q + base + (size_t)(q0 + r) * DD + c * 8);
    }
    CP_COMMIT();

    auto load_kv = [&](int s, int kt) {
        const int k0 = kt * 64;
        #pragma unroll
        for (int i = 0; i < 2; i++) {
            const int t = tid + 256 * i;
            const int r = t >> 3, c = t & 7;
            const uint32_t so = (r * FHPAD + c * 4) * 4;
            cp16(sb + (SM_K0 + s * FKV_U32) * 4 + so,
                 Km + base + (size_t)(k0 + r) * DD + c * 8);
            cp16(sb + (SM_V0 + s * FKV_U32) * 4 + so,
                 Vm + base + (size_t)(k0 + r) * DD + c * 8);
        }
    };

    load_kv(0, 0); CP_COMMIT();
    load_kv(1, 1); CP_COMMIT();

    CP_WAIT2();
    __syncthreads();
    uint32_t qf[4][4];
    #pragma unroll
    for (int ks = 0; ks < 4; ks++)
        LDMX4(qf[ks], sb + (SM_Q + qa_lane + ks * 8) * 4);

    float m0 = -1e30f, m1 = -1e30f;
    float acc_l[4] = {0.0f, 0.0f, 0.0f, 0.0f};   // l via ones-mma
    float acc_o[8][4];
    #pragma unroll
    for (int nt = 0; nt < 8; nt++)
        #pragma unroll
        for (int j = 0; j < 4; j++) acc_o[nt][j] = 0.0f;

    for (int kt = 0; kt < SS / 64; kt++) {
        CP_WAIT1();
        __syncthreads();
        const int s = kt & 1;

        // --- S (log2 units; Q pre-scaled) ---
        float accs[8][4];
        #pragma unroll
        for (int nt = 0; nt < 8; nt++)
            #pragma unroll
            for (int j = 0; j < 4; j++) accs[nt][j] = 0.0f;

        const uint32_t kbase = sb + (SM_K0 + s * FKV_U32 + kb_lane) * 4;
        #pragma unroll
        for (int ks = 0; ks < 4; ks++) {
            #pragma unroll
            for (int nt16 = 0; nt16 < 4; nt16++) {
                uint32_t bb[4];
                LDMX4(bb, kbase + (nt16 * 16 * FHPAD + ks * 8) * 4);
                mma_f16(accs[2 * nt16],     qf[ks], bb[0], bb[1]);
                mma_f16(accs[2 * nt16 + 1], qf[ks], bb[2], bb[3]);
            }
        }

        // --- warp-local max + correction ---
        float nm0 = -1e30f, nm1 = -1e30f;
        #pragma unroll
        for (int nt = 0; nt < 8; nt++) {
            nm0 = fmaxf(nm0, fmaxf(accs[nt][0], accs[nt][1]));
            nm1 = fmaxf(nm1, fmaxf(accs[nt][2], accs[nt][3]));
        }
        nm0 = fmaxf(nm0, __shfl_xor_sync(0xffffffff, nm0, 1));
        nm0 = fmaxf(nm0, __shfl_xor_sync(0xffffffff, nm0, 2));
        nm1 = fmaxf(nm1, __shfl_xor_sync(0xffffffff, nm1, 1));
        nm1 = fmaxf(nm1, __shfl_xor_sync(0xffffffff, nm1, 2));
        nm0 = fmaxf(m0, nm0);
        nm1 = fmaxf(m1, nm1);
        const float corr0 = exp2f(m0 - nm0);
        const float corr1 = exp2f(m1 - nm1);
        m0 = nm0; m1 = nm1;

        // rescale accumulators (incl. l)
        #pragma unroll
        for (int nt = 0; nt < 8; nt++) {
            acc_o[nt][0] *= corr0; acc_o[nt][1] *= corr0;
            acc_o[nt][2] *= corr1; acc_o[nt][3] *= corr1;
        }
        acc_l[0] *= corr0; acc_l[1] *= corr0;
        acc_l[2] *= corr1; acc_l[3] *= corr1;

        // --- P = exp2(S - m) in packed fp16 ---
        uint32_t ph[8][2];
        #pragma unroll
        for (int nt = 0; nt < 8; nt++) {
            __half2 a01 = __floats2half2_rn(accs[nt][0] - m0, accs[nt][1] - m0);
            __half2 a23 = __floats2half2_rn(accs[nt][2] - m1, accs[nt][3] - m1);
            EX2_F16X2(ph[nt][0], *(uint32_t*)&a01);
            EX2_F16X2(ph[nt][1], *(uint32_t*)&a23);
        }

        // --- acc_o += P V ; acc_l += P @ ones ---
        const uint32_t vbase = sb + (SM_V0 + s * FKV_U32 + vb_lane) * 4;
        #pragma unroll
        for (int ks = 0; ks < 4; ks++) {
            const uint32_t a[4] = { ph[2 * ks][0], ph[2 * ks][1],
                                    ph[2 * ks + 1][0], ph[2 * ks + 1][1] };
            mma_f16(acc_l, a, ONES_H2, ONES_H2);
            #pragma unroll
            for (int d16 = 0; d16 < 4; d16++) {
                uint32_t bb[4];
                LDMX4T(bb, vbase + (ks * 16 * FHPAD + d16 * 8) * 4);
                mma_f16(acc_o[2 * d16],     a, bb[0], bb[1]);
                mma_f16(acc_o[2 * d16 + 1], a, bb[2], bb[3]);
            }
        }

        __syncthreads();
        if (kt + 2 < SS / 64) load_kv(s, kt + 2);
        CP_COMMIT();
    }

    // epilogue: divide by l (from ones-mma accumulator), store fp32
    const float li0 = 1.0f / acc_l[0];
    const float li1 = 1.0f / acc_l[2];
    const int r0 = q0 + wid * 16 + g;
    const size_t ro0 = base + (size_t)r0 * DD;
    const size_t ro1 = base + (size_t)(r0 + 8) * DD;
    #pragma unroll
    for (int nt = 0; nt < 8; nt++) {
        const int c = nt * 8 + 2 * t4;
        float2 lo, hi;
        lo.x = acc_o[nt][0] * li0; lo.y = acc_o[nt][1] * li0;
        hi.x = acc_o[nt][2] * li1; hi.y = acc_o[nt][3] * li1;
        *(float2*)(O + ro0 + c) = lo;
        *(float2*)(O + ro1 + c) = hi;
    }
}

// ---------------------------------------------------------------------------
// launch (sequential, default stream)
// ---------------------------------------------------------------------------
extern "C" void kernel_launch(void* const* d_in, const int* in_sizes, int n_in,
                              void* d_out, int out_size)
{
    const float* x      = (const float*)d_in[0];
    const float* alpha1 = (const float*)d_in[1];
    const float* bias1  = (const float*)d_in[2];
    const float* alpha2 = (const float*)d_in[3];
    const float* bias2  = (const float*)d_in[4];
    const float* wq     = (const float*)d_in[5];
    const float* bq     = (const float*)d_in[6];
    const float* wk     = (const float*)d_in[7];
    const float* bk     = (const float*)d_in[8];
    const float* wv     = (const float*)d_in[9];
    const float* bv     = (const float*)d_in[10];
    const float* w1     = (const float*)d_in[11];
    const float* b1     = (const float*)d_in[12];
    const float* w2     = (const float*)d_in[13];
    const float* b2     = (const float*)d_in[14];
    float* out = (float*)d_out;

    __half *p_x2, *p_q, *p_k, *p_v, *p_x2b, *p_h;
    __half *p_wqh, *p_wkh, *p_wvh, *p_w1h, *p_w2h;
    float *p_attn, *p_xres;
    cudaGetSymbolAddress((void**)&p_x2,   g_x2);
    cudaGetSymbolAddress((void**)&p_q,    g_q);
    cudaGetSymbolAddress((void**)&p_k,    g_k);
    cudaGetSymbolAddress((void**)&p_v,    g_v);
    cudaGetSymbolAddress((void**)&p_attn, g_attn);
    cudaGetSymbolAddress((void**)&p_xres, g_xres);
    cudaGetSymbolAddress((void**)&p_x2b,  g_x2b);
    cudaGetSymbolAddress((void**)&p_h,    g_h);
    cudaGetSymbolAddress((void**)&p_wqh,  g_wqh);
    cudaGetSymbolAddress((void**)&p_wkh,  g_wkh);
    cudaGetSymbolAddress((void**)&p_wvh,  g_wvh);
    cudaGetSymbolAddress((void**)&p_w1h,  g_w1h);
    cudaGetSymbolAddress((void**)&p_w2h,  g_w2h);

    cudaFuncSetAttribute(attn_mma,
                         cudaFuncAttributeMaxDynamicSharedMemorySize, FATTN_BYTES);
    cudaFuncSetAttribute(mma_gemm,
                         cudaFuncAttributeMaxDynamicSharedMemorySize, GSMEM_BYTES);

    // 0) convert all weights to half (single fused launch)
    cvt_all_kernel<<<(NCVT4 + 255) / 256, 256>>>(
        wq, wk, wv, w1, w2, p_wqh, p_wkh, p_wvh, p_w1h, p_w2h);

    // 1) norm1 (half out)
    ln_kernel<<<NN, 256>>>(x, nullptr, nullptr, p_x2, alpha1, bias1, 0);

    // 2) fused q,k,v projections; Q output pre-scaled by SCALE*log2(e)
    mma_gemm<<<dim3(DD / MBN, NN / MBM, 3), 256, GSMEM_BYTES>>>(
        p_x2, p_wqh, p_wkh, p_wvh, bq, bk, bv, nullptr,
        p_q, p_k, p_v, nullptr, DD, DD, 0, QSCALE);

    // 3) attention (fp32 out)
    attn_mma<<<dim3(SS / 128, BB * HH), 256, FATTN_BYTES>>>(p_q, p_k, p_v, p_attn);

    // 4) residual + norm2 + mask
    ln_kernel<<<NN, 256>>>(x, p_attn, p_xres, p_x2b, alpha2, bias2, 1);

    // 5) ffn1 + relu (half out)
    mma_gemm<<<dim3(FF / MBN, NN / MBM, 1), 256, GSMEM_BYTES>>>(
        p_x2b, p_w1h, p_w1h, p_w1h, b1, b1, b1, nullptr,
        p_h, p_h, p_h, nullptr, DD, FF, 1, 1.0f);

    // 6) ffn2 + bias + residual -> out (fp32)
    mma_gemm<<<dim3(DD / MBN, NN / MBM, 1), 256, GSMEM_BYTES>>>(
        p_h, p_w2h, p_w2h, p_w2h, b2, b2, b2, p_xres,
        nullptr, nullptr, nullptr, out, FF, DD, 2, 1.0f);
}

// round 15
// speedup vs baseline: 1.0214x; 1.0141x over previous
#include <cuda_runtime.h>
#include <cuda_fp16.h>
#include <math.h>
#include <cstdint>

// ---------------------------------------------------------------------------
// Problem constants
// ---------------------------------------------------------------------------
#define BB 4
#define SS 2048
#define DD 1024
#define HH 16
#define DH 64
#define FF 4096
#define NN (BB * SS)
#define EPS 1e-6f
#define THRESH 0.15f
#define SCALE 0.125f
#define QSCALE 0.1803368801111f   // SCALE * log2(e); folded into Q at projection

// ---------------------------------------------------------------------------
// Scratch (half activations, half weights; fp32 residual path)
// ---------------------------------------------------------------------------
__device__ __half g_x2  [NN * DD];
__device__ __half g_q   [NN * DD];
__device__ __half g_k   [NN * DD];
__device__ __half g_v   [NN * DD];
__device__ float  g_attn[NN * DD];
__device__ float  g_xres[NN * DD];
__device__ __half g_x2b [NN * DD];
__device__ __half g_h   [NN * FF];
__device__ __half g_wqh [DD * DD];
__device__ __half g_wkh [DD * DD];
__device__ __half g_wvh [DD * DD];
__device__ __half g_w1h [FF * DD];
__device__ __half g_w2h [DD * FF];

// ---------------------------------------------------------------------------
// helpers
// ---------------------------------------------------------------------------
__device__ __forceinline__ uint32_t smem_u32(const void* p) {
    uint32_t a;
    asm("{ .reg .u64 t; cvta.to.shared.u64 t, %1; cvt.u32.u64 %0, t; }"
        : "=r"(a) : "l"(p));
    return a;
}

__device__ __forceinline__ void cp16(uint32_t dst, const void* src) {
    asm volatile("cp.async.cg.shared.global [%0], [%1], 16;" :: "r"(dst), "l"(src));
}
#define CP_COMMIT() asm volatile("cp.async.commit_group;" ::: "memory")
#define CP_WAIT1()  asm volatile("cp.async.wait_group 1;" ::: "memory")
#define CP_WAIT2()  asm volatile("cp.async.wait_group 2;" ::: "memory")

__device__ __forceinline__ void mma_f16(float c[4], const uint32_t a[4],
                                        uint32_t b0, uint32_t b1) {
    asm volatile(
        "mma.sync.aligned.m16n8k16.row.col.f32.f16.f16.f32 "
        "{%0,%1,%2,%3}, {%4,%5,%6,%7}, {%8,%9}, {%0,%1,%2,%3};"
        : "+f"(c[0]), "+f"(c[1]), "+f"(c[2]), "+f"(c[3])
        : "r"(a[0]), "r"(a[1]), "r"(a[2]), "r"(a[3]), "r"(b0), "r"(b1));
}

#define LDMX4(r, addr)                                                        \
    asm volatile("ldmatrix.sync.aligned.m8n8.x4.shared.b16 {%0,%1,%2,%3}, [%4];" \
        : "=r"((r)[0]), "=r"((r)[1]), "=r"((r)[2]), "=r"((r)[3]) : "r"(addr))
#define LDMX4T(r, addr)                                                       \
    asm volatile("ldmatrix.sync.aligned.m8n8.x4.trans.shared.b16 {%0,%1,%2,%3}, [%4];" \
        : "=r"((r)[0]), "=r"((r)[1]), "=r"((r)[2]), "=r"((r)[3]) : "r"(addr))

#define EX2_F16X2(d, a) \
    asm("ex2.approx.f16x2 %0, %1;" : "=r"(d) : "r"(a))

// ---------------------------------------------------------------------------
// fused float -> half conversion for ALL weights in one launch
// ---------------------------------------------------------------------------
#define NQKV4 (DD * DD / 4)     // 262144
#define NFF4  (FF * DD / 4)     // 1048576
#define NCVT4 (3 * NQKV4 + 2 * NFF4)

__global__ __launch_bounds__(256) void cvt_all_kernel(
    const float* __restrict__ wq, const float* __restrict__ wk,
    const float* __restrict__ wv, const float* __restrict__ w1,
    const float* __restrict__ w2,
    __half* __restrict__ hq, __half* __restrict__ hk,
    __half* __restrict__ hv, __half* __restrict__ h1,
    __half* __restrict__ h2)
{
    int i = blockIdx.x * 256 + threadIdx.x;
    if (i >= NCVT4) return;
    const float* src;
    __half* dst;
    int off;
    if (i < 3 * NQKV4) {
        const int w = i / NQKV4;
        off = i - w * NQKV4;
        src = (w == 0) ? wq : (w == 1) ? wk : wv;
        dst = (w == 0) ? hq : (w == 1) ? hk : hv;
    } else {
        int j = i - 3 * NQKV4;
        if (j < NFF4) { src = w1; dst = h1; off = j; }
        else          { src = w2; dst = h2; off = j - NFF4; }
    }
    float4 v = ((const float4*)src)[off];
    __half2 h0 = __floats2half2_rn(v.x, v.y);
    __half2 h1v = __floats2half2_rn(v.z, v.w);
    uint2 pk;
    pk.x = *(uint32_t*)&h0;
    pk.y = *(uint32_t*)&h1v;
    ((uint2*)dst)[off] = pk;
}

// ---------------------------------------------------------------------------
// fp16 mma.sync GEMM — R8/R12 structure (unchanged).
// ---------------------------------------------------------------------------
#define MBK  64
#define MBM  128
#define MBN  256
#define APADH 36
#define ASTG (MBM * APADH)
#define BSTG (MBN * APADH)
#define NSTAGE 3
#define GSMEM_BYTES ((ASTG + BSTG) * NSTAGE * 4)

__global__ __launch_bounds__(256, 1) void mma_gemm(
    const __half* __restrict__ A,
    const __half* __restrict__ W0, const __half* __restrict__ W1, const __half* __restrict__ W2,
    const float* __restrict__ bi0, const float* __restrict__ bi1, const float* __restrict__ bi2,
    const float* __restrict__ resid,
    __half* __restrict__ H0, __half* __restrict__ H1, __half* __restrict__ H2,
    float* __restrict__ Cf,
    int K, int ldc, int mode, float oscale0)
{
    extern __shared__ __align__(16) uint32_t smu[];
    const uint32_t sAb = smem_u32(smu);
    const uint32_t sBb = sAb + NSTAGE * ASTG * 4;

    const __half* W    = (blockIdx.z == 0) ? W0  : (blockIdx.z == 1) ? W1  : W2;
    const float*  bias = (blockIdx.z == 0) ? bi0 : (blockIdx.z == 1) ? bi1 : bi2;
    __half*       Ch   = (blockIdx.z == 0) ? H0  : (blockIdx.z == 1) ? H1  : H2;
    const float oscale = (blockIdx.z == 0) ? oscale0 : 1.0f;

    const int tid    = threadIdx.x;
    const int wid    = tid >> 5;
    const int lane   = tid & 31;
    const int warp_m = wid >> 2;
    const int warp_n = wid & 3;
    const int g      = lane >> 2;
    const int t4     = lane & 3;

    const int row0 = blockIdx.y * MBM;
    const int col0 = blockIdx.x * MBN;

    const __half* gA = A + (size_t)row0 * K;
    const __half* gW = W + (size_t)col0 * K;

    const int lrow = tid >> 3;
    const int lch  = tid & 7;

    const uint32_t a_lane = (uint32_t)((warp_m * 64 + (lane & 15)) * APADH + ((lane >> 4) << 2));
    const uint32_t b_lane = (uint32_t)((warp_n * 64 + (lane & 7) + ((lane >> 4) << 3)) * APADH
                                       + (((lane >> 3) & 1) << 2));

    float acc[4][8][4];
    #pragma unroll
    for (int mt = 0; mt < 4; mt++)
        #pragma unroll
        for (int nt = 0; nt < 8; nt++)
            #pragma unroll
            for (int j = 0; j < 4; j++) acc[mt][nt][j] = 0.0f;

    const int NT = K / MBK;

    auto load_stage = [&](int buf, int kt) {
        const size_t kof = (size_t)kt * MBK + lch * 8;
        const uint32_t da = sAb + (buf * ASTG) * 4;
        const uint32_t db = sBb + (buf * BSTG) * 4;
        #pragma unroll
        for (int i = 0; i < 4; i++) {
            const int r = lrow + 32 * i;
            cp16(da + (r * APADH + lch * 4) * 4, gA + (size_t)r * K + kof);
        }
        #pragma unroll
        for (int i = 0; i < 8; i++) {
            const int r = lrow + 32 * i;
            cp16(db + (r * APADH + lch * 4) * 4, gW + (size_t)r * K + kof);
        }
    };

    load_stage(0, 0);
    CP_COMMIT();
    load_stage(1, 1);
    CP_COMMIT();

    int buf = 0;
    for (int t = 0; t < NT; t++) {
        CP_WAIT1();
        __syncthreads();

        const uint32_t abase = sAb + (buf * ASTG + a_lane) * 4;
        const uint32_t bbase = sBb + (buf * BSTG + b_lane) * 4;

        #pragma unroll
        for (int ks = 0; ks < 4; ks++) {
            uint32_t a[4][4], bb[4][4];
            #pragma unroll
            for (int mt = 0; mt < 4; mt++)
                LDMX4(a[mt], abase + (mt * 16 * APADH + ks * 8) * 4);
            #pragma unroll
            for (int ntp = 0; ntp < 4; ntp++)
                LDMX4(bb[ntp], bbase + (ntp * 16 * APADH + ks * 8) * 4);
            #pragma unroll
            for (int mt = 0; mt < 4; mt++)
                #pragma unroll
                for (int ntp = 0; ntp < 4; ntp++) {
                    mma_f16(acc[mt][2 * ntp],     a[mt], bb[ntp][0], bb[ntp][1]);
                    mma_f16(acc[mt][2 * ntp + 1], a[mt], bb[ntp][2], bb[ntp][3]);
                }
        }

        if (t + 2 < NT) {
            load_stage((buf + 2 >= NSTAGE) ? buf + 2 - NSTAGE : buf + 2, t + 2);
        }
        CP_COMMIT();
        buf = (buf + 1 == NSTAGE) ? 0 : buf + 1;
    }

    const int rb = row0 + warp_m * 64 + g;
    const int cb = col0 + warp_n * 64 + t4 * 2;
    #pragma unroll
    for (int mt = 0; mt < 4; mt++) {
        const int r = rb + mt * 16;
        #pragma unroll
        for (int nt = 0; nt < 8; nt++) {
            const int c = cb + nt * 8;
            const float2 bv = *(const float2*)(bias + c);
            float2 v0, v1;
            v0.x = acc[mt][nt][0] + bv.x;
            v0.y = acc[mt][nt][1] + bv.y;
            v1.x = acc[mt][nt][2] + bv.x;
            v1.y = acc[mt][nt][3] + bv.y;
            if (mode == 2) {
                const float2 r0 = *(const float2*)(resid + (size_t)r * ldc + c);
                const float2 r1 = *(const float2*)(resid + (size_t)(r + 8) * ldc + c);
                v0.x += r0.x; v0.y += r0.y;
                v1.x += r1.x; v1.y += r1.y;
                *(float2*)(Cf + (size_t)r * ldc + c)       = v0;
                *(float2*)(Cf + (size_t)(r + 8) * ldc + c) = v1;
            } else {
                if (mode == 1) {
                    v0.x = fmaxf(v0.x, 0.0f); v0.y = fmaxf(v0.y, 0.0f);
                    v1.x = fmaxf(v1.x, 0.0f); v1.y = fmaxf(v1.y, 0.0f);
                } else {
                    v0.x *= oscale; v0.y *= oscale;
                    v1.x *= oscale; v1.y *= oscale;
                }
                __half2 h0 = __floats2half2_rn(v0.x, v0.y);
                __half2 h1 = __floats2half2_rn(v1.x, v1.y);
                *(uint32_t*)(Ch + (size_t)r * ldc + c)       = *(uint32_t*)&h0;
                *(uint32_t*)(Ch + (size_t)(r + 8) * ldc + c) = *(uint32_t*)&h1;
            }
        }
    }
}

// ---------------------------------------------------------------------------
// LayerNorm — half output; fp32 residual in/out; shfl-based reduction (R11)
// ---------------------------------------------------------------------------
__global__ __launch_bounds__(256) void ln_kernel(
    const float* __restrict__ x,
    const float* __restrict__ resid,
    float*       __restrict__ out_res,
    __half*      __restrict__ out_norm,
    const float* __restrict__ alpha,
    const float* __restrict__ beta,
    int apply_mask)
{
    __shared__ float red[18];
    const int n    = blockIdx.x;
    const int tid  = threadIdx.x;
    const int lane = tid & 31;
    const int wrp  = tid >> 5;
    const size_t off = (size_t)n * DD;
    const int d4 = tid * 4;

    float4 xv = *(const float4*)(x + off + d4);
    if (resid) {
        float4 rv = *(const float4*)(resid + off + d4);
        xv.x += rv.x; xv.y += rv.y; xv.z += rv.z; xv.w += rv.w;
    }
    if (out_res) *(float4*)(out_res + off + d4) = xv;

    float s = xv.x + xv.y + xv.z + xv.w;
    #pragma unroll
    for (int o = 16; o > 0; o >>= 1) s += __shfl_xor_sync(0xffffffff, s, o);
    if (lane == 0) red[wrp] = s;
    __syncthreads();
    if (tid < 8) {
        float v = red[tid];
        #pragma unroll
        for (int o = 4; o > 0; o >>= 1) v += __shfl_xor_sync(0x000000ff, v, o);
        if (tid == 0) red[16] = v;
    }
    __syncthreads();
    const float mu = red[16] * (1.0f / DD);

    float dx0 = xv.x - mu, dx1 = xv.y - mu, dx2 = xv.z - mu, dx3 = xv.w - mu;
    float q = dx0*dx0 + dx1*dx1 + dx2*dx2 + dx3*dx3;
    #pragma unroll
    for (int o = 16; o > 0; o >>= 1) q += __shfl_xor_sync(0xffffffff, q, o);
    if (lane == 0) red[8 + wrp] = q;
    __syncthreads();
    if (tid < 8) {
        float v = red[8 + tid];
        #pragma unroll
        for (int o = 4; o > 0; o >>= 1) v += __shfl_xor_sync(0x000000ff, v, o);
        if (tid == 0) red[17] = v;
    }
    __syncthreads();
    const float var = red[17] * (1.0f / (DD - 1));
    const float inv = 1.0f / (sqrtf(var) + EPS);

    float4 av = *(const float4*)(alpha + d4);
    float4 bv = *(const float4*)(beta  + d4);
    float4 y;
    y.x = av.x * dx0 * inv + bv.x;
    y.y = av.y * dx1 * inv + bv.y;
    y.z = av.z * dx2 * inv + bv.z;
    y.w = av.w * dx3 * inv + bv.w;
    if (apply_mask) {
        if (y.x < THRESH) y.x = 0.0f;
        if (y.y < THRESH) y.y = 0.0f;
        if (y.z < THRESH) y.z = 0.0f;
        if (y.w < THRESH) y.w = 0.0f;
    }
    __half2 h0 = __floats2half2_rn(y.x, y.y);
    __half2 h1 = __floats2half2_rn(y.z, y.w);
    uint2 pk;
    pk.x = *(uint32_t*)&h0;
    pk.y = *(uint32_t*)&h1;
    *(uint2*)(out_norm + off + d4) = pk;
}

// ---------------------------------------------------------------------------
// FlashAttention-2 fp16 attention — R12 pipeline (2-slot, 2 barriers),
// P via ex2.approx.f16x2, row-sum via HADD2 over packed P (no extra mma).
// ---------------------------------------------------------------------------
#define FHPAD 36
#define FQ_U32  (128 * FHPAD)
#define FKV_U32 (64 * FHPAD)
#define SM_Q  0
#define SM_K0 (FQ_U32)
#define SM_V0 (FQ_U32 + 2 * FKV_U32)
#define FATTN_BYTES ((FQ_U32 + 4 * FKV_U32) * 4)

__global__ __launch_bounds__(256, 2) void attn_mma(
    const __half* __restrict__ Q,
    const __half* __restrict__ Km,
    const __half* __restrict__ Vm,
    float*        __restrict__ O)
{
    extern __shared__ __align__(16) uint32_t smu[];
    const uint32_t sb = smem_u32(smu);

    const int qb  = blockIdx.x;
    const int bh  = blockIdx.y;
    const int b   = bh >> 4;
    const int h   = bh & 15;
    const int tid = threadIdx.x;
    const int lane = tid & 31;
    const int wid  = tid >> 5;
    const int g    = lane >> 2;
    const int t4   = lane & 3;

    const size_t base = (size_t)b * SS * DD + (size_t)h * DH;
    const int q0 = qb * 128;

    const uint32_t qa_lane = (uint32_t)((wid * 16 + (lane & 15)) * FHPAD + ((lane >> 4) << 2));
    const uint32_t kb_lane = (uint32_t)(((lane & 7) + ((lane >> 4) << 3)) * FHPAD
                                        + (((lane >> 3) & 1) << 2));
    const uint32_t vb_lane = (uint32_t)(((lane & 7) + (((lane >> 3) & 1) << 3)) * FHPAD
                                        + ((lane >> 4) << 2));

    #pragma unroll
    for (int i = 0; i < 4; i++) {
        const int t = tid + 256 * i;
        const int r = t >> 3, c = t & 7;
        cp16(sb + (SM_Q + r * FHPAD + c * 4) * 4,
             Q + base + (size_t)(q0 + r) * DD + c * 8);
    }
    CP_COMMIT();

    auto load_kv = [&](int s, int kt) {
        const int k0 = kt * 64;
        #pragma unroll
        for (int i = 0; i < 2; i++) {
            const int t = tid + 256 * i;
            const int r = t >> 3, c = t & 7;
            const uint32_t so = (r * FHPAD + c * 4) * 4;
            cp16(sb + (SM_K0 + s * FKV_U32) * 4 + so,
                 Km + base + (size_t)(k0 + r) * DD + c * 8);
            cp16(sb + (SM_V0 + s * FKV_U32) * 4 + so,
                 Vm + base + (size_t)(k0 + r) * DD + c * 8);
        }
    };

    load_kv(0, 0); CP_COMMIT();
    load_kv(1, 1); CP_COMMIT();

    CP_WAIT2();
    __syncthreads();
    uint32_t qf[4][4];
    #pragma unroll
    for (int ks = 0; ks < 4; ks++)
        LDMX4(qf[ks], sb + (SM_Q + qa_lane + ks * 8) * 4);

    float m0 = -1e30f, m1 = -1e30f, l0 = 0.0f, l1 = 0.0f;
    float acc_o[8][4];
    #pragma unroll
    for (int nt = 0; nt < 8; nt++)
        #pragma unroll
        for (int j = 0; j < 4; j++) acc_o[nt][j] = 0.0f;

    for (int kt = 0; kt < SS / 64; kt++) {
        CP_WAIT1();
        __syncthreads();
        const int s = kt & 1;

        // --- S (log2 units; Q pre-scaled) ---
        float accs[8][4];
        #pragma unroll
        for (int nt = 0; nt < 8; nt++)
            #pragma unroll
            for (int j = 0; j < 4; j++) accs[nt][j] = 0.0f;

        const uint32_t kbase = sb + (SM_K0 + s * FKV_U32 + kb_lane) * 4;
        #pragma unroll
        for (int ks = 0; ks < 4; ks++) {
            #pragma unroll
            for (int nt16 = 0; nt16 < 4; nt16++) {
                uint32_t bb[4];
                LDMX4(bb, kbase + (nt16 * 16 * FHPAD + ks * 8) * 4);
                mma_f16(accs[2 * nt16],     qf[ks], bb[0], bb[1]);
                mma_f16(accs[2 * nt16 + 1], qf[ks], bb[2], bb[3]);
            }
        }

        // --- warp-local max + correction (base 2) ---
        float nm0 = -1e30f, nm1 = -1e30f;
        #pragma unroll
        for (int nt = 0; nt < 8; nt++) {
            nm0 = fmaxf(nm0, fmaxf(accs[nt][0], accs[nt][1]));
            nm1 = fmaxf(nm1, fmaxf(accs[nt][2], accs[nt][3]));
        }
        nm0 = fmaxf(nm0, __shfl_xor_sync(0xffffffff, nm0, 1));
        nm0 = fmaxf(nm0, __shfl_xor_sync(0xffffffff, nm0, 2));
        nm1 = fmaxf(nm1, __shfl_xor_sync(0xffffffff, nm1, 1));
        nm1 = fmaxf(nm1, __shfl_xor_sync(0xffffffff, nm1, 2));
        nm0 = fmaxf(m0, nm0);
        nm1 = fmaxf(m1, nm1);
        const float corr0 = exp2f(m0 - nm0);
        const float corr1 = exp2f(m1 - nm1);
        m0 = nm0; m1 = nm1;

        // --- P = exp2(S - m) in packed fp16; row-sum via HADD2 ---
        uint32_t ph[8][2];
        __half2 hs0 = __float2half2_rn(0.0f);
        __half2 hs1 = __float2half2_rn(0.0f);
        #pragma unroll
        for (int nt = 0; nt < 8; nt++) {
            __half2 a01 = __floats2half2_rn(accs[nt][0] - m0, accs[nt][1] - m0);
            __half2 a23 = __floats2half2_rn(accs[nt][2] - m1, accs[nt][3] - m1);
            EX2_F16X2(ph[nt][0], *(uint32_t*)&a01);
            EX2_F16X2(ph[nt][1], *(uint32_t*)&a23);
            hs0 = __hadd2(hs0, *(__half2*)&ph[nt][0]);
            hs1 = __hadd2(hs1, *(__half2*)&ph[nt][1]);
        }
        float s0 = __low2float(hs0) + __high2float(hs0);
        float s1 = __low2float(hs1) + __high2float(hs1);
        s0 += __shfl_xor_sync(0xffffffff, s0, 1);
        s0 += __shfl_xor_sync(0xffffffff, s0, 2);
        s1 += __shfl_xor_sync(0xffffffff, s1, 1);
        s1 += __shfl_xor_sync(0xffffffff, s1, 2);
        l0 = l0 * corr0 + s0;
        l1 = l1 * corr1 + s1;

        #pragma unroll
        for (int nt = 0; nt < 8; nt++) {
            acc_o[nt][0] *= corr0; acc_o[nt][1] *= corr0;
            acc_o[nt][2] *= corr1; acc_o[nt][3] *= corr1;
        }

        // --- acc_o += P V ---
        const uint32_t vbase = sb + (SM_V0 + s * FKV_U32 + vb_lane) * 4;
        #pragma unroll
        for (int ks = 0; ks < 4; ks++) {
            const uint32_t a[4] = { ph[2 * ks][0], ph[2 * ks][1],
                                    ph[2 * ks + 1][0], ph[2 * ks + 1][1] };
            #pragma unroll
            for (int d16 = 0; d16 < 4; d16++) {
                uint32_t bb[4];
                LDMX4T(bb, vbase + (ks * 16 * FHPAD + d16 * 8) * 4);
                mma_f16(acc_o[2 * d16],     a, bb[0], bb[1]);
                mma_f16(acc_o[2 * d16 + 1], a, bb[2], bb[3]);
            }
        }

        __syncthreads();
        if (kt + 2 < SS / 64) load_kv(s, kt + 2);
        CP_COMMIT();
    }

    // epilogue: divide by l, store fp32
    const float li0 = 1.0f / l0;
    const float li1 = 1.0f / l1;
    const int r0 = q0 + wid * 16 + g;
    const size_t ro0 = base + (size_t)r0 * DD;
    const size_t ro1 = base + (size_t)(r0 + 8) * DD;
    #pragma unroll
    for (int nt = 0; nt < 8; nt++) {
        const int c = nt * 8 + 2 * t4;
        float2 lo, hi;
        lo.x = acc_o[nt][0] * li0; lo.y = acc_o[nt][1] * li0;
        hi.x = acc_o[nt][2] * li1; hi.y = acc_o[nt][3] * li1;
        *(float2*)(O + ro0 + c) = lo;
        *(float2*)(O + ro1 + c) = hi;
    }
}

// ---------------------------------------------------------------------------
// launch (sequential, default stream)
// ---------------------------------------------------------------------------
extern "C" void kernel_launch(void* const* d_in, const int* in_sizes, int n_in,
                              void* d_out, int out_size)
{
    const float* x      = (const float*)d_in[0];
    const float* alpha1 = (const float*)d_in[1];
    const float* bias1  = (const float*)d_in[2];
    const float* alpha2 = (const float*)d_in[3];
    const float* bias2  = (const float*)d_in[4];
    const float* wq     = (const float*)d_in[5];
    const float* bq     = (const float*)d_in[6];
    const float* wk     = (const float*)d_in[7];
    const float* bk     = (const float*)d_in[8];
    const float* wv     = (const float*)d_in[9];
    const float* bv     = (const float*)d_in[10];
    const float* w1     = (const float*)d_in[11];
    const float* b1     = (const float*)d_in[12];
    const float* w2     = (const float*)d_in[13];
    const float* b2     = (const float*)d_in[14];
    float* out = (float*)d_out;

    __half *p_x2, *p_q, *p_k, *p_v, *p_x2b, *p_h;
    __half *p_wqh, *p_wkh, *p_wvh, *p_w1h, *p_w2h;
    float *p_attn, *p_xres;
    cudaGetSymbolAddress((void**)&p_x2,   g_x2);
    cudaGetSymbolAddress((void**)&p_q,    g_q);
    cudaGetSymbolAddress((void**)&p_k,    g_k);
    cudaGetSymbolAddress((void**)&p_v,    g_v);
    cudaGetSymbolAddress((void**)&p_attn, g_attn);
    cudaGetSymbolAddress((void**)&p_xres, g_xres);
    cudaGetSymbolAddress((void**)&p_x2b,  g_x2b);
    cudaGetSymbolAddress((void**)&p_h,    g_h);
    cudaGetSymbolAddress((void**)&p_wqh,  g_wqh);
    cudaGetSymbolAddress((void**)&p_wkh,  g_wkh);
    cudaGetSymbolAddress((void**)&p_wvh,  g_wvh);
    cudaGetSymbolAddress((void**)&p_w1h,  g_w1h);
    cudaGetSymbolAddress((void**)&p_w2h,  g_w2h);

    cudaFuncSetAttribute(attn_mma,
                         cudaFuncAttributeMaxDynamicSharedMemorySize, FATTN_BYTES);
    cudaFuncSetAttribute(mma_gemm,
                         cudaFuncAttributeMaxDynamicSharedMemorySize, GSMEM_BYTES);

    // 0) convert all weights to half (single fused launch)
    cvt_all_kernel<<<(NCVT4 + 255) / 256, 256>>>(
        wq, wk, wv, w1, w2, p_wqh, p_wkh, p_wvh, p_w1h, p_w2h);

    // 1) norm1 (half out)
    ln_kernel<<<NN, 256>>>(x, nullptr, nullptr, p_x2, alpha1, bias1, 0);

    // 2) fused q,k,v projections; Q output pre-scaled by SCALE*log2(e)
    mma_gemm<<<dim3(DD / MBN, NN / MBM, 3), 256, GSMEM_BYTES>>>(
        p_x2, p_wqh, p_wkh, p_wvh, bq, bk, bv, nullptr,
        p_q, p_k, p_v, nullptr, DD, DD, 0, QSCALE);

    // 3) attention (fp32 out)
    attn_mma<<<dim3(SS / 128, BB * HH), 256, FATTN_BYTES>>>(p_q, p_k, p_v, p_attn);

    // 4) residual + norm2 + mask
    ln_kernel<<<NN, 256>>>(x, p_attn, p_xres, p_x2b, alpha2, bias2, 1);

    // 5) ffn1 + relu (half out)
    mma_gemm<<<dim3(FF / MBN, NN / MBM, 1), 256, GSMEM_BYTES>>>(
        p_x2b, p_w1h, p_w1h, p_w1h, b1, b1, b1, nullptr,
        p_h, p_h, p_h, nullptr, DD, FF, 1, 1.0f);

    // 6) ffn2 + bias + residual -> out (fp32)
    mma_gemm<<<dim3(DD / MBN, NN / MBM, 1), 256, GSMEM_BYTES>>>(
        p_h, p_w2h, p_w2h, p_w2h, b2, b2, b2, p_xres,
        nullptr, nullptr, nullptr, out, FF, DD, 2, 1.0f);
}

// round 16
// speedup vs baseline: 1.0243x; 1.0028x over previous
#include <cuda_runtime.h>
#include <cuda_fp16.h>
#include <math.h>
#include <cstdint>

// ---------------------------------------------------------------------------
// Problem constants
// ---------------------------------------------------------------------------
#define BB 4
#define SS 2048
#define DD 1024
#define HH 16
#define DH 64
#define FF 4096
#define NN (BB * SS)
#define EPS 1e-6f
#define THRESH 0.15f
#define SCALE 0.125f
#define QSCALE 0.1803368801111f   // SCALE * log2(e); folded into Q at projection

// ---------------------------------------------------------------------------
// Scratch (half activations, half weights; fp32 residual path)
// ---------------------------------------------------------------------------
__device__ __half g_x2  [NN * DD];
__device__ __half g_q   [NN * DD];
__device__ __half g_k   [NN * DD];
__device__ __half g_v   [NN * DD];
__device__ float  g_attn[NN * DD];
__device__ float  g_xres[NN * DD];
__device__ __half g_x2b [NN * DD];
__device__ __half g_h   [NN * FF];
__device__ __half g_wqh [DD * DD];
__device__ __half g_wkh [DD * DD];
__device__ __half g_wvh [DD * DD];
__device__ __half g_w1h [FF * DD];
__device__ __half g_w2h [DD * FF];

// ---------------------------------------------------------------------------
// helpers
// ---------------------------------------------------------------------------
__device__ __forceinline__ uint32_t smem_u32(const void* p) {
    uint32_t a;
    asm("{ .reg .u64 t; cvta.to.shared.u64 t, %1; cvt.u32.u64 %0, t; }"
        : "=r"(a) : "l"(p));
    return a;
}

__device__ __forceinline__ void cp16(uint32_t dst, const void* src) {
    asm volatile("cp.async.cg.shared.global [%0], [%1], 16;" :: "r"(dst), "l"(src));
}
#define CP_COMMIT() asm volatile("cp.async.commit_group;" ::: "memory")
#define CP_WAIT1()  asm volatile("cp.async.wait_group 1;" ::: "memory")
#define CP_WAIT2()  asm volatile("cp.async.wait_group 2;" ::: "memory")

__device__ __forceinline__ void mma_f16(float c[4], const uint32_t a[4],
                                        uint32_t b0, uint32_t b1) {
    asm volatile(
        "mma.sync.aligned.m16n8k16.row.col.f32.f16.f16.f32 "
        "{%0,%1,%2,%3}, {%4,%5,%6,%7}, {%8,%9}, {%0,%1,%2,%3};"
        : "+f"(c[0]), "+f"(c[1]), "+f"(c[2]), "+f"(c[3])
        : "r"(a[0]), "r"(a[1]), "r"(a[2]), "r"(a[3]), "r"(b0), "r"(b1));
}

#define LDMX4(r, addr)                                                        \
    asm volatile("ldmatrix.sync.aligned.m8n8.x4.shared.b16 {%0,%1,%2,%3}, [%4];" \
        : "=r"((r)[0]), "=r"((r)[1]), "=r"((r)[2]), "=r"((r)[3]) : "r"(addr))
#define LDMX4T(r, addr)                                                       \
    asm volatile("ldmatrix.sync.aligned.m8n8.x4.trans.shared.b16 {%0,%1,%2,%3}, [%4];" \
        : "=r"((r)[0]), "=r"((r)[1]), "=r"((r)[2]), "=r"((r)[3]) : "r"(addr))

#define EX2_F16X2(d, a) \
    asm("ex2.approx.f16x2 %0, %1;" : "=r"(d) : "r"(a))

// ---------------------------------------------------------------------------
// fused float -> half conversion for ALL weights in one launch
// ---------------------------------------------------------------------------
#define NQKV4 (DD * DD / 4)     // 262144
#define NFF4  (FF * DD / 4)     // 1048576
#define NCVT4 (3 * NQKV4 + 2 * NFF4)

__global__ __launch_bounds__(256) void cvt_all_kernel(
    const float* __restrict__ wq, const float* __restrict__ wk,
    const float* __restrict__ wv, const float* __restrict__ w1,
    const float* __restrict__ w2,
    __half* __restrict__ hq, __half* __restrict__ hk,
    __half* __restrict__ hv, __half* __restrict__ h1,
    __half* __restrict__ h2)
{
    int i = blockIdx.x * 256 + threadIdx.x;
    if (i >= NCVT4) return;
    const float* src;
    __half* dst;
    int off;
    if (i < 3 * NQKV4) {
        const int w = i / NQKV4;
        off = i - w * NQKV4;
        src = (w == 0) ? wq : (w == 1) ? wk : wv;
        dst = (w == 0) ? hq : (w == 1) ? hk : hv;
    } else {
        int j = i - 3 * NQKV4;
        if (j < NFF4) { src = w1; dst = h1; off = j; }
        else          { src = w2; dst = h2; off = j - NFF4; }
    }
    float4 v = ((const float4*)src)[off];
    __half2 h0 = __floats2half2_rn(v.x, v.y);
    __half2 h1v = __floats2half2_rn(v.z, v.w);
    uint2 pk;
    pk.x = *(uint32_t*)&h0;
    pk.y = *(uint32_t*)&h1v;
    ((uint2*)dst)[off] = pk;
}

// ---------------------------------------------------------------------------
// fp16 mma.sync GEMM — R8/R12 structure (unchanged).
// ---------------------------------------------------------------------------
#define MBK  64
#define MBM  128
#define MBN  256
#define APADH 36
#define ASTG (MBM * APADH)
#define BSTG (MBN * APADH)
#define NSTAGE 3
#define GSMEM_BYTES ((ASTG + BSTG) * NSTAGE * 4)

__global__ __launch_bounds__(256, 1) void mma_gemm(
    const __half* __restrict__ A,
    const __half* __restrict__ W0, const __half* __restrict__ W1, const __half* __restrict__ W2,
    const float* __restrict__ bi0, const float* __restrict__ bi1, const float* __restrict__ bi2,
    const float* __restrict__ resid,
    __half* __restrict__ H0, __half* __restrict__ H1, __half* __restrict__ H2,
    float* __restrict__ Cf,
    int K, int ldc, int mode, float oscale0)
{
    extern __shared__ __align__(16) uint32_t smu[];
    const uint32_t sAb = smem_u32(smu);
    const uint32_t sBb = sAb + NSTAGE * ASTG * 4;

    const __half* W    = (blockIdx.z == 0) ? W0  : (blockIdx.z == 1) ? W1  : W2;
    const float*  bias = (blockIdx.z == 0) ? bi0 : (blockIdx.z == 1) ? bi1 : bi2;
    __half*       Ch   = (blockIdx.z == 0) ? H0  : (blockIdx.z == 1) ? H1  : H2;
    const float oscale = (blockIdx.z == 0) ? oscale0 : 1.0f;

    const int tid    = threadIdx.x;
    const int wid    = tid >> 5;
    const int lane   = tid & 31;
    const int warp_m = wid >> 2;
    const int warp_n = wid & 3;
    const int g      = lane >> 2;
    const int t4     = lane & 3;

    const int row0 = blockIdx.y * MBM;
    const int col0 = blockIdx.x * MBN;

    const __half* gA = A + (size_t)row0 * K;
    const __half* gW = W + (size_t)col0 * K;

    const int lrow = tid >> 3;
    const int lch  = tid & 7;

    const uint32_t a_lane = (uint32_t)((warp_m * 64 + (lane & 15)) * APADH + ((lane >> 4) << 2));
    const uint32_t b_lane = (uint32_t)((warp_n * 64 + (lane & 7) + ((lane >> 4) << 3)) * APADH
                                       + (((lane >> 3) & 1) << 2));

    float acc[4][8][4];
    #pragma unroll
    for (int mt = 0; mt < 4; mt++)
        #pragma unroll
        for (int nt = 0; nt < 8; nt++)
            #pragma unroll
            for (int j = 0; j < 4; j++) acc[mt][nt][j] = 0.0f;

    const int NT = K / MBK;

    auto load_stage = [&](int buf, int kt) {
        const size_t kof = (size_t)kt * MBK + lch * 8;
        const uint32_t da = sAb + (buf * ASTG) * 4;
        const uint32_t db = sBb + (buf * BSTG) * 4;
        #pragma unroll
        for (int i = 0; i < 4; i++) {
            const int r = lrow + 32 * i;
            cp16(da + (r * APADH + lch * 4) * 4, gA + (size_t)r * K + kof);
        }
        #pragma unroll
        for (int i = 0; i < 8; i++) {
            const int r = lrow + 32 * i;
            cp16(db + (r * APADH + lch * 4) * 4, gW + (size_t)r * K + kof);
        }
    };

    load_stage(0, 0);
    CP_COMMIT();
    load_stage(1, 1);
    CP_COMMIT();

    int buf = 0;
    for (int t = 0; t < NT; t++) {
        CP_WAIT1();
        __syncthreads();

        const uint32_t abase = sAb + (buf * ASTG + a_lane) * 4;
        const uint32_t bbase = sBb + (buf * BSTG + b_lane) * 4;

        #pragma unroll
        for (int ks = 0; ks < 4; ks++) {
            uint32_t a[4][4], bb[4][4];
            #pragma unroll
            for (int mt = 0; mt < 4; mt++)
                LDMX4(a[mt], abase + (mt * 16 * APADH + ks * 8) * 4);
            #pragma unroll
            for (int ntp = 0; ntp < 4; ntp++)
                LDMX4(bb[ntp], bbase + (ntp * 16 * APADH + ks * 8) * 4);
            #pragma unroll
            for (int mt = 0; mt < 4; mt++)
                #pragma unroll
                for (int ntp = 0; ntp < 4; ntp++) {
                    mma_f16(acc[mt][2 * ntp],     a[mt], bb[ntp][0], bb[ntp][1]);
                    mma_f16(acc[mt][2 * ntp + 1], a[mt], bb[ntp][2], bb[ntp][3]);
                }
        }

        if (t + 2 < NT) {
            load_stage((buf + 2 >= NSTAGE) ? buf + 2 - NSTAGE : buf + 2, t + 2);
        }
        CP_COMMIT();
        buf = (buf + 1 == NSTAGE) ? 0 : buf + 1;
    }

    const int rb = row0 + warp_m * 64 + g;
    const int cb = col0 + warp_n * 64 + t4 * 2;
    #pragma unroll
    for (int mt = 0; mt < 4; mt++) {
        const int r = rb + mt * 16;
        #pragma unroll
        for (int nt = 0; nt < 8; nt++) {
            const int c = cb + nt * 8;
            const float2 bv = *(const float2*)(bias + c);
            float2 v0, v1;
            v0.x = acc[mt][nt][0] + bv.x;
            v0.y = acc[mt][nt][1] + bv.y;
            v1.x = acc[mt][nt][2] + bv.x;
            v1.y = acc[mt][nt][3] + bv.y;
            if (mode == 2) {
                const float2 r0 = *(const float2*)(resid + (size_t)r * ldc + c);
                const float2 r1 = *(const float2*)(resid + (size_t)(r + 8) * ldc + c);
                v0.x += r0.x; v0.y += r0.y;
                v1.x += r1.x; v1.y += r1.y;
                *(float2*)(Cf + (size_t)r * ldc + c)       = v0;
                *(float2*)(Cf + (size_t)(r + 8) * ldc + c) = v1;
            } else {
                if (mode == 1) {
                    v0.x = fmaxf(v0.x, 0.0f); v0.y = fmaxf(v0.y, 0.0f);
                    v1.x = fmaxf(v1.x, 0.0f); v1.y = fmaxf(v1.y, 0.0f);
                } else {
                    v0.x *= oscale; v0.y *= oscale;
                    v1.x *= oscale; v1.y *= oscale;
                }
                __half2 h0 = __floats2half2_rn(v0.x, v0.y);
                __half2 h1 = __floats2half2_rn(v1.x, v1.y);
                *(uint32_t*)(Ch + (size_t)r * ldc + c)       = *(uint32_t*)&h0;
                *(uint32_t*)(Ch + (size_t)(r + 8) * ldc + c) = *(uint32_t*)&h1;
            }
        }
    }
}

// ---------------------------------------------------------------------------
// LayerNorm — half output; fp32 residual in/out; shfl-based reduction (R11)
// ---------------------------------------------------------------------------
__global__ __launch_bounds__(256) void ln_kernel(
    const float* __restrict__ x,
    const float* __restrict__ resid,
    float*       __restrict__ out_res,
    __half*      __restrict__ out_norm,
    const float* __restrict__ alpha,
    const float* __restrict__ beta,
    int apply_mask)
{
    __shared__ float red[18];
    const int n    = blockIdx.x;
    const int tid  = threadIdx.x;
    const int lane = tid & 31;
    const int wrp  = tid >> 5;
    const size_t off = (size_t)n * DD;
    const int d4 = tid * 4;

    float4 xv = *(const float4*)(x + off + d4);
    if (resid) {
        float4 rv = *(const float4*)(resid + off + d4);
        xv.x += rv.x; xv.y += rv.y; xv.z += rv.z; xv.w += rv.w;
    }
    if (out_res) *(float4*)(out_res + off + d4) = xv;

    float s = xv.x + xv.y + xv.z + xv.w;
    #pragma unroll
    for (int o = 16; o > 0; o >>= 1) s += __shfl_xor_sync(0xffffffff, s, o);
    if (lane == 0) red[wrp] = s;
    __syncthreads();
    if (tid < 8) {
        float v = red[tid];
        #pragma unroll
        for (int o = 4; o > 0; o >>= 1) v += __shfl_xor_sync(0x000000ff, v, o);
        if (tid == 0) red[16] = v;
    }
    __syncthreads();
    const float mu = red[16] * (1.0f / DD);

    float dx0 = xv.x - mu, dx1 = xv.y - mu, dx2 = xv.z - mu, dx3 = xv.w - mu;
    float q = dx0*dx0 + dx1*dx1 + dx2*dx2 + dx3*dx3;
    #pragma unroll
    for (int o = 16; o > 0; o >>= 1) q += __shfl_xor_sync(0xffffffff, q, o);
    if (lane == 0) red[8 + wrp] = q;
    __syncthreads();
    if (tid < 8) {
        float v = red[8 + tid];
        #pragma unroll
        for (int o = 4; o > 0; o >>= 1) v += __shfl_xor_sync(0x000000ff, v, o);
        if (tid == 0) red[17] = v;
    }
    __syncthreads();
    const float var = red[17] * (1.0f / (DD - 1));
    const float inv = 1.0f / (sqrtf(var) + EPS);

    float4 av = *(const float4*)(alpha + d4);
    float4 bv = *(const float4*)(beta  + d4);
    float4 y;
    y.x = av.x * dx0 * inv + bv.x;
    y.y = av.y * dx1 * inv + bv.y;
    y.z = av.z * dx2 * inv + bv.z;
    y.w = av.w * dx3 * inv + bv.w;
    if (apply_mask) {
        if (y.x < THRESH) y.x = 0.0f;
        if (y.y < THRESH) y.y = 0.0f;
        if (y.z < THRESH) y.z = 0.0f;
        if (y.w < THRESH) y.w = 0.0f;
    }
    __half2 h0 = __floats2half2_rn(y.x, y.y);
    __half2 h1 = __floats2half2_rn(y.z, y.w);
    uint2 pk;
    pk.x = *(uint32_t*)&h0;
    pk.y = *(uint32_t*)&h1;
    *(uint2*)(out_norm + off + d4) = pk;
}

// ---------------------------------------------------------------------------
// FlashAttention-2 fp16 attention — 4 warps x 32 q-rows (2 m16 tiles/warp):
// K/V ldmatrix amortized over 2x mmas. R15 softmax (ex2.f16x2 + HADD2 sums).
// ---------------------------------------------------------------------------
#define FHPAD 36
#define FQ_U32  (128 * FHPAD)
#define FKV_U32 (64 * FHPAD)
#define SM_Q  0
#define SM_K0 (FQ_U32)
#define SM_V0 (FQ_U32 + 2 * FKV_U32)
#define FATTN_BYTES ((FQ_U32 + 4 * FKV_U32) * 4)

__global__ __launch_bounds__(128, 2) void attn_mma(
    const __half* __restrict__ Q,
    const __half* __restrict__ Km,
    const __half* __restrict__ Vm,
    float*        __restrict__ O)
{
    extern __shared__ __align__(16) uint32_t smu[];
    const uint32_t sb = smem_u32(smu);

    const int qb  = blockIdx.x;
    const int bh  = blockIdx.y;
    const int b   = bh >> 4;
    const int h   = bh & 15;
    const int tid = threadIdx.x;
    const int lane = tid & 31;
    const int wid  = tid >> 5;              // 0..3, owns rows wid*32..+31
    const int g    = lane >> 2;
    const int t4   = lane & 3;

    const size_t base = (size_t)b * SS * DD + (size_t)h * DH;
    const int q0 = qb * 128;

    const uint32_t kb_lane = (uint32_t)(((lane & 7) + ((lane >> 4) << 3)) * FHPAD
                                        + (((lane >> 3) & 1) << 2));
    const uint32_t vb_lane = (uint32_t)(((lane & 7) + (((lane >> 3) & 1) << 3)) * FHPAD
                                        + ((lane >> 4) << 2));

    // Q load: 1024 chunks / 128 threads = 8 each
    #pragma unroll
    for (int i = 0; i < 8; i++) {
        const int t = tid + 128 * i;
        const int r = t >> 3, c = t & 7;
        cp16(sb + (SM_Q + r * FHPAD + c * 4) * 4,
             Q + base + (size_t)(q0 + r) * DD + c * 8);
    }
    CP_COMMIT();

    auto load_kv = [&](int s, int kt) {
        const int k0 = kt * 64;
        #pragma unroll
        for (int i = 0; i < 4; i++) {
            const int t = tid + 128 * i;
            const int r = t >> 3, c = t & 7;
            const uint32_t so = (r * FHPAD + c * 4) * 4;
            cp16(sb + (SM_K0 + s * FKV_U32) * 4 + so,
                 Km + base + (size_t)(k0 + r) * DD + c * 8);
            cp16(sb + (SM_V0 + s * FKV_U32) * 4 + so,
                 Vm + base + (size_t)(k0 + r) * DD + c * 8);
        }
    };

    load_kv(0, 0); CP_COMMIT();
    load_kv(1, 1); CP_COMMIT();

    CP_WAIT2();
    __syncthreads();
    uint32_t qf[2][4][4];
    #pragma unroll
    for (int mt = 0; mt < 2; mt++) {
        const uint32_t qa = (uint32_t)((wid * 32 + mt * 16 + (lane & 15)) * FHPAD
                                       + ((lane >> 4) << 2));
        #pragma unroll
        for (int ks = 0; ks < 4; ks++)
            LDMX4(qf[mt][ks], sb + (SM_Q + qa + ks * 8) * 4);
    }

    float m0a[2] = {-1e30f, -1e30f}, m1a[2] = {-1e30f, -1e30f};
    float l0a[2] = {0.0f, 0.0f},     l1a[2] = {0.0f, 0.0f};
    float acc_o[2][8][4];
    #pragma unroll
    for (int mt = 0; mt < 2; mt++)
        #pragma unroll
        for (int nt = 0; nt < 8; nt++)
            #pragma unroll
            for (int j = 0; j < 4; j++) acc_o[mt][nt][j] = 0.0f;

    for (int kt = 0; kt < SS / 64; kt++) {
        CP_WAIT1();
        __syncthreads();
        const int s = kt & 1;

        // --- S = Q K^T (both m-tiles share each K fragment) ---
        float accs[2][8][4];
        #pragma unroll
        for (int mt = 0; mt < 2; mt++)
            #pragma unroll
            for (int nt = 0; nt < 8; nt++)
                #pragma unroll
                for (int j = 0; j < 4; j++) accs[mt][nt][j] = 0.0f;

        const uint32_t kbase = sb + (SM_K0 + s * FKV_U32 + kb_lane) * 4;
        #pragma unroll
        for (int ks = 0; ks < 4; ks++) {
            #pragma unroll
            for (int nt16 = 0; nt16 < 4; nt16++) {
                uint32_t bb[4];
                LDMX4(bb, kbase + (nt16 * 16 * FHPAD + ks * 8) * 4);
                #pragma unroll
                for (int mt = 0; mt < 2; mt++) {
                    mma_f16(accs[mt][2 * nt16],     qf[mt][ks], bb[0], bb[1]);
                    mma_f16(accs[mt][2 * nt16 + 1], qf[mt][ks], bb[2], bb[3]);
                }
            }
        }

        // --- softmax per m-tile (base 2, fp16 exp, HADD2 sums) ---
        uint32_t ph[2][8][2];
        #pragma unroll
        for (int mt = 0; mt < 2; mt++) {
            float nm0 = -1e30f, nm1 = -1e30f;
            #pragma unroll
            for (int nt = 0; nt < 8; nt++) {
                nm0 = fmaxf(nm0, fmaxf(accs[mt][nt][0], accs[mt][nt][1]));
                nm1 = fmaxf(nm1, fmaxf(accs[mt][nt][2], accs[mt][nt][3]));
            }
            nm0 = fmaxf(nm0, __shfl_xor_sync(0xffffffff, nm0, 1));
            nm0 = fmaxf(nm0, __shfl_xor_sync(0xffffffff, nm0, 2));
            nm1 = fmaxf(nm1, __shfl_xor_sync(0xffffffff, nm1, 1));
            nm1 = fmaxf(nm1, __shfl_xor_sync(0xffffffff, nm1, 2));
            nm0 = fmaxf(m0a[mt], nm0);
            nm1 = fmaxf(m1a[mt], nm1);
            const float corr0 = exp2f(m0a[mt] - nm0);
            const float corr1 = exp2f(m1a[mt] - nm1);
            m0a[mt] = nm0; m1a[mt] = nm1;

            __half2 hs0 = __float2half2_rn(0.0f);
            __half2 hs1 = __float2half2_rn(0.0f);
            #pragma unroll
            for (int nt = 0; nt < 8; nt++) {
                __half2 a01 = __floats2half2_rn(accs[mt][nt][0] - nm0,
                                                accs[mt][nt][1] - nm0);
                __half2 a23 = __floats2half2_rn(accs[mt][nt][2] - nm1,
                                                accs[mt][nt][3] - nm1);
                EX2_F16X2(ph[mt][nt][0], *(uint32_t*)&a01);
                EX2_F16X2(ph[mt][nt][1], *(uint32_t*)&a23);
                hs0 = __hadd2(hs0, *(__half2*)&ph[mt][nt][0]);
                hs1 = __hadd2(hs1, *(__half2*)&ph[mt][nt][1]);
            }
            float s0 = __low2float(hs0) + __high2float(hs0);
            float s1 = __low2float(hs1) + __high2float(hs1);
            s0 += __shfl_xor_sync(0xffffffff, s0, 1);
            s0 += __shfl_xor_sync(0xffffffff, s0, 2);
            s1 += __shfl_xor_sync(0xffffffff, s1, 1);
            s1 += __shfl_xor_sync(0xffffffff, s1, 2);
            l0a[mt] = l0a[mt] * corr0 + s0;
            l1a[mt] = l1a[mt] * corr1 + s1;

            #pragma unroll
            for (int nt = 0; nt < 8; nt++) {
                acc_o[mt][nt][0] *= corr0; acc_o[mt][nt][1] *= corr0;
                acc_o[mt][nt][2] *= corr1; acc_o[mt][nt][3] *= corr1;
            }
        }

        // --- acc_o += P V (both m-tiles share each V fragment) ---
        const uint32_t vbase = sb + (SM_V0 + s * FKV_U32 + vb_lane) * 4;
        #pragma unroll
        for (int ks = 0; ks < 4; ks++) {
            #pragma unroll
            for (int d16 = 0; d16 < 4; d16++) {
                uint32_t bb[4];
                LDMX4T(bb, vbase + (ks * 16 * FHPAD + d16 * 8) * 4);
                #pragma unroll
                for (int mt = 0; mt < 2; mt++) {
                    const uint32_t a[4] = { ph[mt][2 * ks][0], ph[mt][2 * ks][1],
                                            ph[mt][2 * ks + 1][0], ph[mt][2 * ks + 1][1] };
                    mma_f16(acc_o[mt][2 * d16],     a, bb[0], bb[1]);
                    mma_f16(acc_o[mt][2 * d16 + 1], a, bb[2], bb[3]);
                }
            }
        }

        __syncthreads();
        if (kt + 2 < SS / 64) load_kv(s, kt + 2);
        CP_COMMIT();
    }

    // epilogue
    #pragma unroll
    for (int mt = 0; mt < 2; mt++) {
        const float li0 = 1.0f / l0a[mt];
        const float li1 = 1.0f / l1a[mt];
        const int r0 = q0 + wid * 32 + mt * 16 + g;
        const size_t ro0 = base + (size_t)r0 * DD;
        const size_t ro1 = base + (size_t)(r0 + 8) * DD;
        #pragma unroll
        for (int nt = 0; nt < 8; nt++) {
            const int c = nt * 8 + 2 * t4;
            float2 lo, hi;
            lo.x = acc_o[mt][nt][0] * li0; lo.y = acc_o[mt][nt][1] * li0;
            hi.x = acc_o[mt][nt][2] * li1; hi.y = acc_o[mt][nt][3] * li1;
            *(float2*)(O + ro0 + c) = lo;
            *(float2*)(O + ro1 + c) = hi;
        }
    }
}

// ---------------------------------------------------------------------------
// launch (sequential, default stream)
// ---------------------------------------------------------------------------
extern "C" void kernel_launch(void* const* d_in, const int* in_sizes, int n_in,
                              void* d_out, int out_size)
{
    const float* x      = (const float*)d_in[0];
    const float* alpha1 = (const float*)d_in[1];
    const float* bias1  = (const float*)d_in[2];
    const float* alpha2 = (const float*)d_in[3];
    const float* bias2  = (const float*)d_in[4];
    const float* wq     = (const float*)d_in[5];
    const float* bq     = (const float*)d_in[6];
    const float* wk     = (const float*)d_in[7];
    const float* bk     = (const float*)d_in[8];
    const float* wv     = (const float*)d_in[9];
    const float* bv     = (const float*)d_in[10];
    const float* w1     = (const float*)d_in[11];
    const float* b1     = (const float*)d_in[12];
    const float* w2     = (const float*)d_in[13];
    const float* b2     = (const float*)d_in[14];
    float* out = (float*)d_out;

    __half *p_x2, *p_q, *p_k, *p_v, *p_x2b, *p_h;
    __half *p_wqh, *p_wkh, *p_wvh, *p_w1h, *p_w2h;
    float *p_attn, *p_xres;
    cudaGetSymbolAddress((void**)&p_x2,   g_x2);
    cudaGetSymbolAddress((void**)&p_q,    g_q);
    cudaGetSymbolAddress((void**)&p_k,    g_k);
    cudaGetSymbolAddress((void**)&p_v,    g_v);
    cudaGetSymbolAddress((void**)&p_attn, g_attn);
    cudaGetSymbolAddress((void**)&p_xres, g_xres);
    cudaGetSymbolAddress((void**)&p_x2b,  g_x2b);
    cudaGetSymbolAddress((void**)&p_h,    g_h);
    cudaGetSymbolAddress((void**)&p_wqh,  g_wqh);
    cudaGetSymbolAddress((void**)&p_wkh,  g_wkh);
    cudaGetSymbolAddress((void**)&p_wvh,  g_wvh);
    cudaGetSymbolAddress((void**)&p_w1h,  g_w1h);
    cudaGetSymbolAddress((void**)&p_w2h,  g_w2h);

    cudaFuncSetAttribute(attn_mma,
                         cudaFuncAttributeMaxDynamicSharedMemorySize, FATTN_BYTES);
    cudaFuncSetAttribute(mma_gemm,
                         cudaFuncAttributeMaxDynamicSharedMemorySize, GSMEM_BYTES);

    // 0) convert all weights to half (single fused launch)
    cvt_all_kernel<<<(NCVT4 + 255) / 256, 256>>>(
        wq, wk, wv, w1, w2, p_wqh, p_wkh, p_wvh, p_w1h, p_w2h);

    // 1) norm1 (half out)
    ln_kernel<<<NN, 256>>>(x, nullptr, nullptr, p_x2, alpha1, bias1, 0);

    // 2) fused q,k,v projections; Q output pre-scaled by SCALE*log2(e)
    mma_gemm<<<dim3(DD / MBN, NN / MBM, 3), 256, GSMEM_BYTES>>>(
        p_x2, p_wqh, p_wkh, p_wvh, bq, bk, bv, nullptr,
        p_q, p_k, p_v, nullptr, DD, DD, 0, QSCALE);

    // 3) attention (fp32 out, 128 threads / 4 warps per CTA)
    attn_mma<<<dim3(SS / 128, BB * HH), 128, FATTN_BYTES>>>(p_q, p_k, p_v, p_attn);

    // 4) residual + norm2 + mask
    ln_kernel<<<NN, 256>>>(x, p_attn, p_xres, p_x2b, alpha2, bias2, 1);

    // 5) ffn1 + relu (half out)
    mma_gemm<<<dim3(FF / MBN, NN / MBM, 1), 256, GSMEM_BYTES>>>(
        p_x2b, p_w1h, p_w1h, p_w1h, b1, b1, b1, nullptr,
        p_h, p_h, p_h, nullptr, DD, FF, 1, 1.0f);

    // 6) ffn2 + bias + residual -> out (fp32)
    mma_gemm<<<dim3(DD / MBN, NN / MBM, 1), 256, GSMEM_BYTES>>>(
        p_h, p_w2h, p_w2h, p_w2h, b2, b2, b2, p_xres,
        nullptr, nullptr, nullptr, out, FF, DD, 2, 1.0f);
}